// round 2
// baseline (speedup 1.0000x reference)
#include <cuda_runtime.h>

#define LL 9
#define BB 4
#define CC 512
#define HW 1024

// ---------------- scratch (device globals; no allocation) ----------------
__device__ __align__(16) float g_invq[LL*BB*HW];
__device__ __align__(16) float g_invs[LL*BB*HW];
__device__ __align__(16) float g_corr[(size_t)BB*HW*HW];   // 16 MB, reused as attn
__device__ __align__(16) float g_c1[BB*256*HW];            // conv1 out [b][256][32*32]
__device__ __align__(16) float g_c2[BB*256*900];           // conv2 out [b][256][30*30]
__device__ __align__(16) float g_pool[BB*256*100];         // pooled [b][256][10*10]
__device__ __align__(16) float g_wt1[9*1024*256];          // w1 transposed [tap][ic][oc]
__device__ __align__(16) float g_wt2[9*256*256];           // w2 transposed [tap][ic][oc]
__device__ __align__(16) float g_nq2[BB*HW];
__device__ __align__(16) float g_na2[BB*HW];

// ---------------- helpers ----------------
__device__ __forceinline__ void fma44(float (&acc)[4][4], float4 a, float4 b) {
    acc[0][0] = fmaf(a.x, b.x, acc[0][0]); acc[0][1] = fmaf(a.x, b.y, acc[0][1]);
    acc[0][2] = fmaf(a.x, b.z, acc[0][2]); acc[0][3] = fmaf(a.x, b.w, acc[0][3]);
    acc[1][0] = fmaf(a.y, b.x, acc[1][0]); acc[1][1] = fmaf(a.y, b.y, acc[1][1]);
    acc[1][2] = fmaf(a.y, b.z, acc[1][2]); acc[1][3] = fmaf(a.y, b.w, acc[1][3]);
    acc[2][0] = fmaf(a.z, b.x, acc[2][0]); acc[2][1] = fmaf(a.z, b.y, acc[2][1]);
    acc[2][2] = fmaf(a.z, b.z, acc[2][2]); acc[2][3] = fmaf(a.z, b.w, acc[2][3]);
    acc[3][0] = fmaf(a.w, b.x, acc[3][0]); acc[3][1] = fmaf(a.w, b.y, acc[3][1]);
    acc[3][2] = fmaf(a.w, b.z, acc[3][2]); acc[3][3] = fmaf(a.w, b.w, acc[3][3]);
}

// ---------------- weight transposes: w[oc][ic][tap] -> wt[tap][ic][oc] ----------------
__global__ void k_twt1(const float* __restrict__ w1) {
    int i = blockIdx.x * 256 + threadIdx.x;          // < 2359296
    float v = w1[i];
    int oc = i / 9216; int r = i % 9216; int ic = r / 9; int tap = r % 9;
    g_wt1[tap * 262144 + ic * 256 + oc] = v;
}
__global__ void k_twt2(const float* __restrict__ w2) {
    int i = blockIdx.x * 256 + threadIdx.x;          // < 589824
    float v = w2[i];
    int oc = i / 2304; int r = i % 2304; int ic = r / 9; int tap = r % 9;
    g_wt2[tap * 65536 + ic * 256 + oc] = v;
}

// ---------------- per-level per-pixel inverse channel norms ----------------
__global__ void k_norms(const float* __restrict__ fq, const float* __restrict__ fs) {
    int lb  = blockIdx.y;                             // 0..35 (l*B+b)
    int pix = blockIdx.x * 256 + threadIdx.x;         // 0..1023
    const float* src = (blockIdx.z == 0 ? fq : fs) + (size_t)lb * CC * HW + pix;
    float ss = 0.f;
#pragma unroll 8
    for (int c = 0; c < CC; c++) { float v = src[(size_t)c * HW]; ss = fmaf(v, v, ss); }
    float inv = 1.0f / fmaxf(sqrtf(ss), 1e-12f);
    (blockIdx.z == 0 ? g_invq : g_invs)[lb * HW + pix] = inv;
}

// ---------------- corr: g_corr = sum_l relu( (fq_l . fs_l) * invq * invs ) ----------------
// Per (l,b): C[m,n] = sum_k A[k,m]*B[k,n], A,B stored [512][1024] (m/n contiguous).
// 128x128 tile, 8x8 microtile, Kt=8 double-buffered; ReLU-accumulate across levels
// via L2-resident global RMW of the CTA-private output tile.
__global__ void __launch_bounds__(256, 2) k_corr(const float* __restrict__ fq,
                                                 const float* __restrict__ fs) {
    __shared__ __align__(16) float As[2][8][128];
    __shared__ __align__(16) float Bs[2][8][128];
    int b  = blockIdx.z;
    int m0 = blockIdx.y * 128, n0 = blockIdx.x * 128;
    int tid = threadIdx.x, tx = tid & 15, ty = tid >> 4;
    int lr = tid >> 5, lc = (tid & 31) * 4;           // ldg coords: 8 rows x 32 float4

    float* outp = g_corr + (size_t)b * HW * HW + (size_t)m0 * HW + n0;

    for (int l = 0; l < LL; l++) {
        const float* A  = fq + (size_t)(l * BB + b) * CC * HW + m0;
        const float* Bp = fs + (size_t)(l * BB + b) * CC * HW + n0;

        float acc[8][8];
#pragma unroll
        for (int i = 0; i < 8; i++)
#pragma unroll
            for (int j = 0; j < 8; j++) acc[i][j] = 0.f;

        __syncthreads();                              // smem reuse across levels
        // prologue: tile 0
        float4 av = *(const float4*)(A  + (size_t)lr * HW + lc);
        float4 bv = *(const float4*)(Bp + (size_t)lr * HW + lc);
        *(float4*)&As[0][lr][lc] = av;
        *(float4*)&Bs[0][lr][lc] = bv;
        __syncthreads();

        int buf = 0;
        for (int kt = 0; kt < 64; kt++) {
            if (kt < 63) {
                int k0 = (kt + 1) * 8;
                av = *(const float4*)(A  + (size_t)(k0 + lr) * HW + lc);
                bv = *(const float4*)(Bp + (size_t)(k0 + lr) * HW + lc);
            }
#pragma unroll
            for (int k = 0; k < 8; k++) {
                float4 a0 = *(const float4*)&As[buf][k][ty * 8];
                float4 a1 = *(const float4*)&As[buf][k][ty * 8 + 4];
                float4 b0 = *(const float4*)&Bs[buf][k][tx * 8];
                float4 b1 = *(const float4*)&Bs[buf][k][tx * 8 + 4];
                float am[8] = {a0.x, a0.y, a0.z, a0.w, a1.x, a1.y, a1.z, a1.w};
                float bn[8] = {b0.x, b0.y, b0.z, b0.w, b1.x, b1.y, b1.z, b1.w};
#pragma unroll
                for (int i = 0; i < 8; i++)
#pragma unroll
                    for (int j = 0; j < 8; j++)
                        acc[i][j] = fmaf(am[i], bn[j], acc[i][j]);
            }
            if (kt < 63) {
                *(float4*)&As[buf ^ 1][lr][lc] = av;
                *(float4*)&Bs[buf ^ 1][lr][lc] = bv;
                __syncthreads();
                buf ^= 1;
            }
        }

        // per-level epilogue: scale, relu, accumulate into global tile (L2-resident)
        const float* iq = g_invq + (l * BB + b) * HW + m0 + ty * 8;
        const float* is = g_invs + (l * BB + b) * HW + n0 + tx * 8;
        float qv[8], sv[8];
#pragma unroll
        for (int i = 0; i < 8; i++) { qv[i] = iq[i]; sv[i] = is[i]; }
#pragma unroll
        for (int i = 0; i < 8; i++) {
            float r[8];
#pragma unroll
            for (int j = 0; j < 8; j++) r[j] = fmaxf(acc[i][j] * qv[i] * sv[j], 0.f);
            float* p = outp + (size_t)(ty * 8 + i) * HW + tx * 8;
            if (l == 0) {
                *(float4*)p       = make_float4(r[0], r[1], r[2], r[3]);
                *(float4*)(p + 4) = make_float4(r[4], r[5], r[6], r[7]);
            } else {
                float4 o0 = *(const float4*)p, o1 = *(const float4*)(p + 4);
                o0.x += r[0]; o0.y += r[1]; o0.z += r[2]; o0.w += r[3];
                o1.x += r[4]; o1.y += r[5]; o1.z += r[6]; o1.w += r[7];
                *(float4*)p = o0; *(float4*)(p + 4) = o1;
            }
        }
    }
}

// ---------------- row softmax (scale = TEMP/L folds the mean) ----------------
__global__ void k_softmax() {
    float* r = g_corr + (size_t)blockIdx.x * HW;      // blockIdx.x = b*1024 + q
    int tid = threadIdx.x, wid = tid >> 5, lane = tid & 31;
    const float sc = 20.0f / 9.0f;
    float4 v = ((const float4*)r)[tid];
    v.x *= sc; v.y *= sc; v.z *= sc; v.w *= sc;
    float mx = fmaxf(fmaxf(v.x, v.y), fmaxf(v.z, v.w));
#pragma unroll
    for (int o = 16; o; o >>= 1) mx = fmaxf(mx, __shfl_xor_sync(0xffffffffu, mx, o));
    __shared__ float sh[8];
    if (lane == 0) sh[wid] = mx;
    __syncthreads();
    float m = sh[0];
#pragma unroll
    for (int k = 1; k < 8; k++) m = fmaxf(m, sh[k]);
    v.x = __expf(v.x - m); v.y = __expf(v.y - m);
    v.z = __expf(v.z - m); v.w = __expf(v.w - m);
    float s = v.x + v.y + v.z + v.w;
#pragma unroll
    for (int o = 16; o; o >>= 1) s += __shfl_xor_sync(0xffffffffu, s, o);
    __syncthreads();
    if (lane == 0) sh[wid] = s;
    __syncthreads();
    float tot = 0.f;
#pragma unroll
    for (int k = 0; k < 8; k++) tot += sh[k];
    float inv = 1.0f / tot;
    v.x *= inv; v.y *= inv; v.z *= inv; v.w *= inv;
    ((float4*)r)[tid] = v;
}

// ---------------- att_fq[b,c,q] = sum_s attn[b,q,s] * f_s[b,c,s]  (NT gemm) ----------------
__global__ void k_att(const float* __restrict__ fs_in, float* __restrict__ attout) {
    __shared__ __align__(16) float As[16][68];
    __shared__ __align__(16) float Bs[16][68];
    int b  = blockIdx.z;
    int m0 = blockIdx.y * 64;   // c
    int n0 = blockIdx.x * 64;   // q
    int tid = threadIdx.x, tx = tid & 15, ty = tid >> 4;
    int lm = tid >> 2, lk = (tid & 3) * 4;            // 64 rows, 4 k each

    const float* A  = fs_in + (size_t)b * CC * HW;    // [512][1024] (k=s contig)
    const float* Bm = g_corr + (size_t)b * HW * HW;   // attn [1024][1024] (k=s contig)

    float acc[4][4];
#pragma unroll
    for (int i = 0; i < 4; i++)
#pragma unroll
        for (int j = 0; j < 4; j++) acc[i][j] = 0.f;

    for (int kt = 0; kt < 64; kt++) {
        int k0 = kt * 16;
        float4 a4 = *(const float4*)(A  + (size_t)(m0 + lm) * HW + k0 + lk);
        float4 b4 = *(const float4*)(Bm + (size_t)(n0 + lm) * HW + k0 + lk);
        As[lk + 0][lm] = a4.x; As[lk + 1][lm] = a4.y; As[lk + 2][lm] = a4.z; As[lk + 3][lm] = a4.w;
        Bs[lk + 0][lm] = b4.x; Bs[lk + 1][lm] = b4.y; Bs[lk + 2][lm] = b4.z; Bs[lk + 3][lm] = b4.w;
        __syncthreads();
#pragma unroll
        for (int k2 = 0; k2 < 16; k2++) {
            float4 av = *(const float4*)&As[k2][ty * 4];
            float4 bv = *(const float4*)&Bs[k2][tx * 4];
            fma44(acc, av, bv);
        }
        __syncthreads();
    }
    float* outp = attout + (size_t)b * CC * HW + (size_t)m0 * HW + n0;
#pragma unroll
    for (int i = 0; i < 4; i++) {
        float4 o = make_float4(acc[i][0], acc[i][1], acc[i][2], acc[i][3]);
        *(float4*)(outp + (size_t)(ty * 4 + i) * HW + tx * 4) = o;
    }
}

// ---------------- inverse channel norms of f_q and att_fq ----------------
__global__ void k_norm2(const float* __restrict__ f_q, const float* __restrict__ att) {
    int b   = blockIdx.y;
    int pix = blockIdx.x * 256 + threadIdx.x;
    const float* src = (blockIdx.z == 0 ? f_q : att) + (size_t)b * CC * HW + pix;
    float ss = 0.f;
#pragma unroll 8
    for (int c = 0; c < CC; c++) { float v = src[(size_t)c * HW]; ss = fmaf(v, v, ss); }
    float inv = 1.0f / fmaxf(sqrtf(ss), 1e-12f);
    (blockIdx.z == 0 ? g_nq2 : g_na2)[b * HW + pix] = inv;
}

// ---------------- fq = l2n(f_q) + 0.5*l2n(att_fq) ----------------
__global__ void k_fqout(const float* __restrict__ f_q, const float* __restrict__ att,
                        float* __restrict__ fqo) {
    int i4 = blockIdx.x * 256 + threadIdx.x;          // < 524288
    int base = i4 * 4;
    int b = base >> 19;
    int pix = base & 1023;
    float4 q = ((const float4*)f_q)[i4];
    float4 a = ((const float4*)att)[i4];
    int ni = (b * HW + pix) >> 2;
    float4 nq = ((const float4*)g_nq2)[ni];
    float4 na = ((const float4*)g_na2)[ni];
    float4 o;
    o.x = q.x * nq.x + a.x * na.x * 0.5f;
    o.y = q.y * nq.y + a.y * na.y * 0.5f;
    o.z = q.z * nq.z + a.z * na.z * 0.5f;
    o.w = q.w * nq.w + a.w * na.w * 0.5f;
    ((float4*)fqo)[i4] = o;
}

// ---------------- conv1: implicit GEMM 64(oc)x128(pix), 4x8 micro, Kt=8 double-buffered ----------------
__global__ void __launch_bounds__(256, 2) k_conv1(const float* __restrict__ f_q,
                                                  const float* __restrict__ f_s,
                                                  const float* __restrict__ b1) {
    __shared__ __align__(16) float Ws[2][8][64];
    __shared__ __align__(16) float Is[2][8][128];
    int nt = blockIdx.x;                              // 0..31: global pixel tile
    int b = nt >> 3;                                  // 1024 pix per b / 128 = 8 tiles
    int pix0 = (nt & 7) * 128;
    int oc0 = blockIdx.y * 64;
    int tid = threadIdx.x, tx = tid & 15, ty = tid >> 4;
    const float* fqp = f_q + (size_t)b * CC * HW;
    const float* fsp = f_s + (size_t)b * CC * HW;

    // ldg coords: input 8 rows x 32x4 pixels; weights (threads<128) 8 rows x 16x4 oc
    int ir = tid >> 5, ip = (tid & 31) * 4;
    int wr = tid >> 4, wc = (tid & 15) * 4;
    int py[4], px[4];
#pragma unroll
    for (int j = 0; j < 4; j++) { int p = pix0 + ip + j; py[j] = p >> 5; px[j] = p & 31; }

    float acc[4][8];
#pragma unroll
    for (int i = 0; i < 4; i++)
#pragma unroll
        for (int j = 0; j < 8; j++) acc[i][j] = 0.f;

    // prefetch helper (kt in [0,1152))
    float4 wv; float iv[4];
    {
        int tap = 0, icb = 0;
        int dy = -2, dx = -2;
        if (tid < 128)
            wv = *(const float4*)(g_wt1 + tap * 262144 + (icb + wr) * 256 + oc0 + wc);
        int ic = icb + ir;
        const float* src = (ic < 512 ? fqp + (size_t)ic * HW : fsp + (size_t)(ic - 512) * HW);
#pragma unroll
        for (int j = 0; j < 4; j++) {
            int iy = py[j] + dy, ix = px[j] + dx;
            iv[j] = (((unsigned)iy < 32u) && ((unsigned)ix < 32u)) ? src[iy * 32 + ix] : 0.f;
        }
    }
    if (tid < 128) *(float4*)&Ws[0][wr][wc] = wv;
#pragma unroll
    for (int j = 0; j < 4; j++) Is[0][ir][ip + j] = iv[j];
    __syncthreads();

    int buf = 0;
    for (int kt = 0; kt < 1152; kt++) {
        if (kt < 1151) {
            int kn = kt + 1;
            int tap = kn >> 7, icb = (kn & 127) * 8;
            int dy = 2 * (tap / 3) - 2, dx = 2 * (tap % 3) - 2;
            if (tid < 128)
                wv = *(const float4*)(g_wt1 + tap * 262144 + (icb + wr) * 256 + oc0 + wc);
            int ic = icb + ir;
            const float* src = (ic < 512 ? fqp + (size_t)ic * HW : fsp + (size_t)(ic - 512) * HW);
#pragma unroll
            for (int j = 0; j < 4; j++) {
                int iy = py[j] + dy, ix = px[j] + dx;
                iv[j] = (((unsigned)iy < 32u) && ((unsigned)ix < 32u)) ? src[iy * 32 + ix] : 0.f;
            }
        }
#pragma unroll
        for (int k = 0; k < 8; k++) {
            float4 w4 = *(const float4*)&Ws[buf][k][ty * 4];
            float4 i0 = *(const float4*)&Is[buf][k][tx * 8];
            float4 i1 = *(const float4*)&Is[buf][k][tx * 8 + 4];
            float wm[4] = {w4.x, w4.y, w4.z, w4.w};
            float in[8] = {i0.x, i0.y, i0.z, i0.w, i1.x, i1.y, i1.z, i1.w};
#pragma unroll
            for (int i = 0; i < 4; i++)
#pragma unroll
                for (int j = 0; j < 8; j++)
                    acc[i][j] = fmaf(wm[i], in[j], acc[i][j]);
        }
        if (kt < 1151) {
            if (tid < 128) *(float4*)&Ws[buf ^ 1][wr][wc] = wv;
#pragma unroll
            for (int j = 0; j < 4; j++) Is[buf ^ 1][ir][ip + j] = iv[j];
            __syncthreads();
            buf ^= 1;
        }
    }

    float* outp = g_c1 + (size_t)b * 262144;
#pragma unroll
    for (int i = 0; i < 4; i++) {
        int oc = oc0 + ty * 4 + i;
        float bias = b1[oc];
        float* p = outp + (size_t)oc * HW + pix0 + tx * 8;
        *(float4*)p       = make_float4(fmaxf(acc[i][0] + bias, 0.f), fmaxf(acc[i][1] + bias, 0.f),
                                        fmaxf(acc[i][2] + bias, 0.f), fmaxf(acc[i][3] + bias, 0.f));
        *(float4*)(p + 4) = make_float4(fmaxf(acc[i][4] + bias, 0.f), fmaxf(acc[i][5] + bias, 0.f),
                                        fmaxf(acc[i][6] + bias, 0.f), fmaxf(acc[i][7] + bias, 0.f));
    }
}

// ---------------- conv2: implicit GEMM, 3x3 VALID on 32x32 -> 30x30, +bias ----------------
__global__ void k_conv2(const float* __restrict__ b2) {
    __shared__ __align__(16) float Ws[16][64];
    __shared__ __align__(16) float Is[16][64];
    int b = blockIdx.z, oc0 = blockIdx.y * 64, n0 = blockIdx.x * 64;
    int tid = threadIdx.x, tx = tid & 15, ty = tid >> 4;
    int kk = (tid * 4) >> 6, nn0 = (tid * 4) & 63;

    int py[4], px[4];
#pragma unroll
    for (int j = 0; j < 4; j++) {
        int p = n0 + nn0 + j; if (p > 899) p = 899;
        py[j] = p / 30; px[j] = p % 30;
    }

    float acc[4][4];
#pragma unroll
    for (int i = 0; i < 4; i++)
#pragma unroll
        for (int j = 0; j < 4; j++) acc[i][j] = 0.f;

    for (int tap = 0; tap < 9; tap++) {
        int dy = tap / 3, dx = tap % 3;
        int off[4];
#pragma unroll
        for (int j = 0; j < 4; j++) off[j] = (py[j] + dy) * 32 + (px[j] + dx);
        const float* wb = g_wt2 + tap * 65536 + oc0;
        for (int ict = 0; ict < 16; ict++) {
            int ic0 = ict * 16;
            float4 wv = *(const float4*)(wb + (ic0 + kk) * 256 + nn0);
            *(float4*)&Ws[kk][nn0] = wv;
            const float* ib = g_c1 + (size_t)b * 262144 + (size_t)(ic0 + kk) * HW;
#pragma unroll
            for (int j = 0; j < 4; j++) Is[kk][nn0 + j] = ib[off[j]];
            __syncthreads();
#pragma unroll
            for (int k2 = 0; k2 < 16; k2++) {
                float4 w4 = *(const float4*)&Ws[k2][ty * 4];
                float4 i4 = *(const float4*)&Is[k2][tx * 4];
                fma44(acc, w4, i4);
            }
            __syncthreads();
        }
    }
#pragma unroll
    for (int i = 0; i < 4; i++) {
        int oc = oc0 + ty * 4 + i;
        float bias = b2[oc];
#pragma unroll
        for (int j = 0; j < 4; j++) {
            int p = n0 + tx * 4 + j;
            if (p < 900) g_c2[(size_t)b * 230400 + (size_t)oc * 900 + p] = acc[i][j] + bias;
        }
    }
}

// ---------------- 3x3 stride-3 maxpool: 30x30 -> 10x10 ----------------
__global__ void k_pool() {
    int oc = blockIdx.x, b = blockIdx.y;
    int t = threadIdx.x;
    if (t >= 100) return;
    int y = t / 10, x = t % 10;
    const float* in = g_c2 + ((size_t)b * 256 + oc) * 900;
    float m = -3.4e38f;
#pragma unroll
    for (int dy = 0; dy < 3; dy++)
#pragma unroll
        for (int dx = 0; dx < 3; dx++)
            m = fmaxf(m, in[(3 * y + dy) * 30 + 3 * x + dx]);
    g_pool[((size_t)b * 256 + oc) * 100 + t] = m;
}

// ---------------- conv3 (3x3 VALID, 10x10 -> 8x8) + mean -> weight[b] ----------------
__global__ void k_conv3(const float* __restrict__ w3, const float* __restrict__ b3,
                        float* __restrict__ wout) {
    int b = blockIdx.x;
    int tid = threadIdx.x;
    int o = tid >> 2, part = tid & 3;         // 64 outputs x 4 partial sums
    int oy = o >> 3, ox = o & 7;
    float s = 0.f;
    for (int ic = part * 64; ic < part * 64 + 64; ic++) {
        const float* pp = g_pool + ((size_t)b * 256 + ic) * 100 + oy * 10 + ox;
        const float* wp = w3 + ic * 9;
#pragma unroll
        for (int ky = 0; ky < 3; ky++)
#pragma unroll
            for (int kx = 0; kx < 3; kx++)
                s = fmaf(pp[ky * 10 + kx], wp[ky * 3 + kx], s);
    }
    s += __shfl_down_sync(0xffffffffu, s, 1);
    s += __shfl_down_sync(0xffffffffu, s, 2);
    __shared__ float sh[64];
    if (part == 0) sh[o] = s;
    __syncthreads();
    if (tid < 32) {
        float v = sh[tid] + sh[tid + 32];
#pragma unroll
        for (int off = 16; off; off >>= 1) v += __shfl_xor_sync(0xffffffffu, v, off);
        if (tid == 0) wout[b] = v * (1.0f / 64.0f) + b3[0];
    }
}

// ---------------- launch ----------------
extern "C" void kernel_launch(void* const* d_in, const int* in_sizes, int n_in,
                              void* d_out, int out_size) {
    const float* fq_feats = (const float*)d_in[0];
    const float* fs_feats = (const float*)d_in[1];
    const float* f_q = (const float*)d_in[2];
    const float* f_s = (const float*)d_in[3];
    const float* w1 = (const float*)d_in[4];
    const float* b1 = (const float*)d_in[5];
    const float* w2 = (const float*)d_in[6];
    const float* b2 = (const float*)d_in[7];
    const float* w3 = (const float*)d_in[8];
    const float* b3 = (const float*)d_in[9];

    float* out     = (float*)d_out;
    float* fq_out  = out;                       // [4,512,32,32]
    float* att_out = out + 2097152;             // [4,512,32,32]
    float* w_out   = out + 4194304;             // [1,4]

    k_twt1<<<9216, 256>>>(w1);
    k_twt2<<<2304, 256>>>(w2);
    k_norms<<<dim3(4, 36, 2), 256>>>(fq_feats, fs_feats);
    k_corr<<<dim3(8, 8, 4), 256>>>(fq_feats, fs_feats);
    k_softmax<<<4096, 256>>>();
    k_att<<<dim3(16, 8, 4), 256>>>(f_s, att_out);
    k_norm2<<<dim3(4, 4, 2), 256>>>(f_q, att_out);
    k_fqout<<<2048, 256>>>(f_q, att_out, fq_out);
    k_conv1<<<dim3(32, 4), 256>>>(f_q, f_s, b1);
    k_conv2<<<dim3(15, 4, 4), 256>>>(b2);
    k_pool<<<dim3(256, 4), 128>>>();
    k_conv3<<<4, 256>>>(w3, b3, w_out);
}

// round 3
// speedup vs baseline: 1.3906x; 1.3906x over previous
#include <cuda_runtime.h>

#define LL 9
#define BB 4
#define CC 512
#define HW 1024

// ---------------- scratch (device globals; no allocation) ----------------
__device__ __align__(16) float g_invq[LL*BB*HW];
__device__ __align__(16) float g_invs[LL*BB*HW];
__device__ __align__(16) float g_corr[(size_t)BB*HW*HW];   // 16 MB, reused as attn
__device__ __align__(16) float g_c1[BB*256*HW];            // conv1 out [b][256][32*32]
__device__ __align__(16) float g_c2[BB*256*900];           // conv2 out [b][256][30*30]
__device__ __align__(16) float g_pool[BB*256*100];         // pooled [b][256][10*10]
__device__ __align__(16) float g_wt1[9*1024*256];          // w1 transposed [tap][ic][oc]
__device__ __align__(16) float g_wt2[9*256*256];           // w2 transposed [tap][ic][oc]
__device__ __align__(16) float g_nq2[BB*HW];
__device__ __align__(16) float g_na2[BB*HW];

// ---------------- helpers ----------------
__device__ __forceinline__ void fma44(float (&acc)[4][4], float4 a, float4 b) {
    acc[0][0] = fmaf(a.x, b.x, acc[0][0]); acc[0][1] = fmaf(a.x, b.y, acc[0][1]);
    acc[0][2] = fmaf(a.x, b.z, acc[0][2]); acc[0][3] = fmaf(a.x, b.w, acc[0][3]);
    acc[1][0] = fmaf(a.y, b.x, acc[1][0]); acc[1][1] = fmaf(a.y, b.y, acc[1][1]);
    acc[1][2] = fmaf(a.y, b.z, acc[1][2]); acc[1][3] = fmaf(a.y, b.w, acc[1][3]);
    acc[2][0] = fmaf(a.z, b.x, acc[2][0]); acc[2][1] = fmaf(a.z, b.y, acc[2][1]);
    acc[2][2] = fmaf(a.z, b.z, acc[2][2]); acc[2][3] = fmaf(a.z, b.w, acc[2][3]);
    acc[3][0] = fmaf(a.w, b.x, acc[3][0]); acc[3][1] = fmaf(a.w, b.y, acc[3][1]);
    acc[3][2] = fmaf(a.w, b.z, acc[3][2]); acc[3][3] = fmaf(a.w, b.w, acc[3][3]);
}

// ---------------- weight transposes: w[oc][ic][tap] -> wt[tap][ic][oc] ----------------
__global__ void k_twt1(const float* __restrict__ w1) {
    int i = blockIdx.x * 256 + threadIdx.x;          // < 2359296
    float v = w1[i];
    int oc = i / 9216; int r = i % 9216; int ic = r / 9; int tap = r % 9;
    g_wt1[tap * 262144 + ic * 256 + oc] = v;
}
__global__ void k_twt2(const float* __restrict__ w2) {
    int i = blockIdx.x * 256 + threadIdx.x;          // < 589824
    float v = w2[i];
    int oc = i / 2304; int r = i % 2304; int ic = r / 9; int tap = r % 9;
    g_wt2[tap * 65536 + ic * 256 + oc] = v;
}

// ---------------- per-level per-pixel inverse channel norms ----------------
__global__ void k_norms(const float* __restrict__ fq, const float* __restrict__ fs) {
    int lb  = blockIdx.y;                             // 0..35 (l*B+b)
    int pix = blockIdx.x * 256 + threadIdx.x;         // 0..1023
    const float* src = (blockIdx.z == 0 ? fq : fs) + (size_t)lb * CC * HW + pix;
    float ss = 0.f;
#pragma unroll 8
    for (int c = 0; c < CC; c++) { float v = src[(size_t)c * HW]; ss = fmaf(v, v, ss); }
    float inv = 1.0f / fmaxf(sqrtf(ss), 1e-12f);
    (blockIdx.z == 0 ? g_invq : g_invs)[lb * HW + pix] = inv;
}

// ---------------- corr: g_corr = sum_l relu( (fq_l . fs_l) * invq * invs ) ----------------
// Per (l,b): C[m,n] = sum_k A[k,m]*B[k,n], A,B stored [512][1024] (m/n contiguous).
// 128x128 tile, 8 threads own quadrant microtile rows {ty*4+i, 64+ty*4+i} x
// cols {tx*4+j, 64+tx*4+j} -> all smem reads are lane-contiguous float4 (conflict-free).
// ReLU-accumulate across levels via L2-resident global RMW of the CTA-private tile.
__global__ void __launch_bounds__(256, 2) k_corr(const float* __restrict__ fq,
                                                 const float* __restrict__ fs) {
    __shared__ __align__(16) float As[2][8][128];
    __shared__ __align__(16) float Bs[2][8][128];
    int b  = blockIdx.z;
    int m0 = blockIdx.y * 128, n0 = blockIdx.x * 128;
    int tid = threadIdx.x, tx = tid & 15, ty = tid >> 4;
    int lr = tid >> 5, lc = (tid & 31) * 4;           // ldg coords: 8 rows x 32 float4

    float* outp = g_corr + (size_t)b * HW * HW + (size_t)m0 * HW + n0;

    for (int l = 0; l < LL; l++) {
        const float* A  = fq + (size_t)(l * BB + b) * CC * HW + m0;
        const float* Bp = fs + (size_t)(l * BB + b) * CC * HW + n0;

        float acc[8][8];
#pragma unroll
        for (int i = 0; i < 8; i++)
#pragma unroll
            for (int j = 0; j < 8; j++) acc[i][j] = 0.f;

        __syncthreads();                              // smem reuse across levels
        float4 av = *(const float4*)(A  + (size_t)lr * HW + lc);
        float4 bv = *(const float4*)(Bp + (size_t)lr * HW + lc);
        *(float4*)&As[0][lr][lc] = av;
        *(float4*)&Bs[0][lr][lc] = bv;
        __syncthreads();

        int buf = 0;
        for (int kt = 0; kt < 64; kt++) {
            if (kt < 63) {
                int k0 = (kt + 1) * 8;
                av = *(const float4*)(A  + (size_t)(k0 + lr) * HW + lc);
                bv = *(const float4*)(Bp + (size_t)(k0 + lr) * HW + lc);
            }
#pragma unroll
            for (int k = 0; k < 8; k++) {
                float4 a0 = *(const float4*)&As[buf][k][ty * 4];
                float4 a1 = *(const float4*)&As[buf][k][64 + ty * 4];
                float4 b0 = *(const float4*)&Bs[buf][k][tx * 4];
                float4 b1 = *(const float4*)&Bs[buf][k][64 + tx * 4];
                float am[8] = {a0.x, a0.y, a0.z, a0.w, a1.x, a1.y, a1.z, a1.w};
                float bn[8] = {b0.x, b0.y, b0.z, b0.w, b1.x, b1.y, b1.z, b1.w};
#pragma unroll
                for (int i = 0; i < 8; i++)
#pragma unroll
                    for (int j = 0; j < 8; j++)
                        acc[i][j] = fmaf(am[i], bn[j], acc[i][j]);
            }
            if (kt < 63) {
                *(float4*)&As[buf ^ 1][lr][lc] = av;
                *(float4*)&Bs[buf ^ 1][lr][lc] = bv;
                __syncthreads();
                buf ^= 1;
            }
        }

        // per-level epilogue: scale, relu, accumulate into global tile (L2-resident)
        const float* iq = g_invq + (l * BB + b) * HW + m0;
        const float* is = g_invs + (l * BB + b) * HW + n0;
        float qv[8], sv[8];
#pragma unroll
        for (int i = 0; i < 4; i++) {
            qv[i]     = iq[ty * 4 + i];
            qv[4 + i] = iq[64 + ty * 4 + i];
            sv[i]     = is[tx * 4 + i];
            sv[4 + i] = is[64 + tx * 4 + i];
        }
#pragma unroll
        for (int i = 0; i < 8; i++) {
            int row = (i < 4) ? (ty * 4 + i) : (64 + ty * 4 + i - 4);
            float r[8];
#pragma unroll
            for (int j = 0; j < 8; j++) r[j] = fmaxf(acc[i][j] * qv[i] * sv[j], 0.f);
            float* p0 = outp + (size_t)row * HW + tx * 4;
            float* p1 = p0 + 64;
            if (l == 0) {
                *(float4*)p0 = make_float4(r[0], r[1], r[2], r[3]);
                *(float4*)p1 = make_float4(r[4], r[5], r[6], r[7]);
            } else {
                float4 o0 = *(const float4*)p0, o1 = *(const float4*)p1;
                o0.x += r[0]; o0.y += r[1]; o0.z += r[2]; o0.w += r[3];
                o1.x += r[4]; o1.y += r[5]; o1.z += r[6]; o1.w += r[7];
                *(float4*)p0 = o0; *(float4*)p1 = o1;
            }
        }
    }
}

// ---------------- row softmax (scale = TEMP/L folds the mean) ----------------
__global__ void k_softmax() {
    float* r = g_corr + (size_t)blockIdx.x * HW;      // blockIdx.x = b*1024 + q
    int tid = threadIdx.x, wid = tid >> 5, lane = tid & 31;
    const float sc = 20.0f / 9.0f;
    float4 v = ((const float4*)r)[tid];
    v.x *= sc; v.y *= sc; v.z *= sc; v.w *= sc;
    float mx = fmaxf(fmaxf(v.x, v.y), fmaxf(v.z, v.w));
#pragma unroll
    for (int o = 16; o; o >>= 1) mx = fmaxf(mx, __shfl_xor_sync(0xffffffffu, mx, o));
    __shared__ float sh[8];
    if (lane == 0) sh[wid] = mx;
    __syncthreads();
    float m = sh[0];
#pragma unroll
    for (int k = 1; k < 8; k++) m = fmaxf(m, sh[k]);
    v.x = __expf(v.x - m); v.y = __expf(v.y - m);
    v.z = __expf(v.z - m); v.w = __expf(v.w - m);
    float s = v.x + v.y + v.z + v.w;
#pragma unroll
    for (int o = 16; o; o >>= 1) s += __shfl_xor_sync(0xffffffffu, s, o);
    __syncthreads();
    if (lane == 0) sh[wid] = s;
    __syncthreads();
    float tot = 0.f;
#pragma unroll
    for (int k = 0; k < 8; k++) tot += sh[k];
    float inv = 1.0f / tot;
    v.x *= inv; v.y *= inv; v.z *= inv; v.w *= inv;
    ((float4*)r)[tid] = v;
}

// ---------------- att_fq[b,c,q] = sum_s attn[b,q,s] * f_s[b,c,s]  (NT gemm) ----------------
__global__ void k_att(const float* __restrict__ fs_in, float* __restrict__ attout) {
    __shared__ __align__(16) float As[16][68];
    __shared__ __align__(16) float Bs[16][68];
    int b  = blockIdx.z;
    int m0 = blockIdx.y * 64;   // c
    int n0 = blockIdx.x * 64;   // q
    int tid = threadIdx.x, tx = tid & 15, ty = tid >> 4;
    int lm = tid >> 2, lk = (tid & 3) * 4;            // 64 rows, 4 k each

    const float* A  = fs_in + (size_t)b * CC * HW;    // [512][1024] (k=s contig)
    const float* Bm = g_corr + (size_t)b * HW * HW;   // attn [1024][1024] (k=s contig)

    float acc[4][4];
#pragma unroll
    for (int i = 0; i < 4; i++)
#pragma unroll
        for (int j = 0; j < 4; j++) acc[i][j] = 0.f;

    for (int kt = 0; kt < 64; kt++) {
        int k0 = kt * 16;
        float4 a4 = *(const float4*)(A  + (size_t)(m0 + lm) * HW + k0 + lk);
        float4 b4 = *(const float4*)(Bm + (size_t)(n0 + lm) * HW + k0 + lk);
        As[lk + 0][lm] = a4.x; As[lk + 1][lm] = a4.y; As[lk + 2][lm] = a4.z; As[lk + 3][lm] = a4.w;
        Bs[lk + 0][lm] = b4.x; Bs[lk + 1][lm] = b4.y; Bs[lk + 2][lm] = b4.z; Bs[lk + 3][lm] = b4.w;
        __syncthreads();
#pragma unroll
        for (int k2 = 0; k2 < 16; k2++) {
            float4 av = *(const float4*)&As[k2][ty * 4];
            float4 bv = *(const float4*)&Bs[k2][tx * 4];
            fma44(acc, av, bv);
        }
        __syncthreads();
    }
    float* outp = attout + (size_t)b * CC * HW + (size_t)m0 * HW + n0;
#pragma unroll
    for (int i = 0; i < 4; i++) {
        float4 o = make_float4(acc[i][0], acc[i][1], acc[i][2], acc[i][3]);
        *(float4*)(outp + (size_t)(ty * 4 + i) * HW + tx * 4) = o;
    }
}

// ---------------- inverse channel norms of f_q and att_fq ----------------
__global__ void k_norm2(const float* __restrict__ f_q, const float* __restrict__ att) {
    int b   = blockIdx.y;
    int pix = blockIdx.x * 256 + threadIdx.x;
    const float* src = (blockIdx.z == 0 ? f_q : att) + (size_t)b * CC * HW + pix;
    float ss = 0.f;
#pragma unroll 8
    for (int c = 0; c < CC; c++) { float v = src[(size_t)c * HW]; ss = fmaf(v, v, ss); }
    float inv = 1.0f / fmaxf(sqrtf(ss), 1e-12f);
    (blockIdx.z == 0 ? g_nq2 : g_na2)[b * HW + pix] = inv;
}

// ---------------- fq = l2n(f_q) + 0.5*l2n(att_fq) ----------------
__global__ void k_fqout(const float* __restrict__ f_q, const float* __restrict__ att,
                        float* __restrict__ fqo) {
    int i4 = blockIdx.x * 256 + threadIdx.x;          // < 524288
    int base = i4 * 4;
    int b = base >> 19;
    int pix = base & 1023;
    float4 q = ((const float4*)f_q)[i4];
    float4 a = ((const float4*)att)[i4];
    int ni = (b * HW + pix) >> 2;
    float4 nq = ((const float4*)g_nq2)[ni];
    float4 na = ((const float4*)g_na2)[ni];
    float4 o;
    o.x = q.x * nq.x + a.x * na.x * 0.5f;
    o.y = q.y * nq.y + a.y * na.y * 0.5f;
    o.z = q.z * nq.z + a.z * na.z * 0.5f;
    o.w = q.w * nq.w + a.w * na.w * 0.5f;
    ((float4*)fqo)[i4] = o;
}

// ---------------- conv1: implicit GEMM, input concat(f_q,f_s), dil=2, pad=2, +bias, relu ----------------
__global__ void k_conv1(const float* __restrict__ f_q, const float* __restrict__ f_s,
                        const float* __restrict__ b1) {
    __shared__ __align__(16) float Ws[16][64];
    __shared__ __align__(16) float Is[16][64];
    int b = blockIdx.z, oc0 = blockIdx.y * 64, n0 = blockIdx.x * 64;
    int tid = threadIdx.x, tx = tid & 15, ty = tid >> 4;
    int kk = (tid * 4) >> 6, nn0 = (tid * 4) & 63;
    const float* fqp = f_q + (size_t)b * CC * HW;
    const float* fsp = f_s + (size_t)b * CC * HW;

    int py[4], px[4];
#pragma unroll
    for (int j = 0; j < 4; j++) { int p = n0 + nn0 + j; py[j] = p >> 5; px[j] = p & 31; }

    float acc[4][4];
#pragma unroll
    for (int i = 0; i < 4; i++)
#pragma unroll
        for (int j = 0; j < 4; j++) acc[i][j] = 0.f;

    for (int tap = 0; tap < 9; tap++) {
        int dy = 2 * (tap / 3) - 2, dx = 2 * (tap % 3) - 2;
        int off[4]; bool inb[4];
#pragma unroll
        for (int j = 0; j < 4; j++) {
            int iy = py[j] + dy, ix = px[j] + dx;
            inb[j] = ((unsigned)iy < 32u) && ((unsigned)ix < 32u);
            off[j] = iy * 32 + ix;
        }
        const float* wb = g_wt1 + tap * 262144 + oc0;
        for (int ict = 0; ict < 64; ict++) {
            int ic0 = ict * 16;
            float4 wv = *(const float4*)(wb + (ic0 + kk) * 256 + nn0);
            *(float4*)&Ws[kk][nn0] = wv;
            const float* ib = (ic0 < 512 ? fqp + (size_t)ic0 * HW
                                         : fsp + (size_t)(ic0 - 512) * HW) + (size_t)kk * HW;
#pragma unroll
            for (int j = 0; j < 4; j++) Is[kk][nn0 + j] = inb[j] ? ib[off[j]] : 0.f;
            __syncthreads();
#pragma unroll
            for (int k2 = 0; k2 < 16; k2++) {
                float4 w4 = *(const float4*)&Ws[k2][ty * 4];
                float4 i4 = *(const float4*)&Is[k2][tx * 4];
                fma44(acc, w4, i4);
            }
            __syncthreads();
        }
    }
    float* outp = g_c1 + (size_t)b * 262144;
#pragma unroll
    for (int i = 0; i < 4; i++) {
        int oc = oc0 + ty * 4 + i;
        float bias = b1[oc];
        float4 o = make_float4(fmaxf(acc[i][0] + bias, 0.f), fmaxf(acc[i][1] + bias, 0.f),
                               fmaxf(acc[i][2] + bias, 0.f), fmaxf(acc[i][3] + bias, 0.f));
        *(float4*)(outp + (size_t)oc * HW + n0 + tx * 4) = o;
    }
}

// ---------------- conv2: implicit GEMM, 3x3 VALID on 32x32 -> 30x30, +bias ----------------
__global__ void k_conv2(const float* __restrict__ b2) {
    __shared__ __align__(16) float Ws[16][64];
    __shared__ __align__(16) float Is[16][64];
    int b = blockIdx.z, oc0 = blockIdx.y * 64, n0 = blockIdx.x * 64;
    int tid = threadIdx.x, tx = tid & 15, ty = tid >> 4;
    int kk = (tid * 4) >> 6, nn0 = (tid * 4) & 63;

    int py[4], px[4];
#pragma unroll
    for (int j = 0; j < 4; j++) {
        int p = n0 + nn0 + j; if (p > 899) p = 899;
        py[j] = p / 30; px[j] = p % 30;
    }

    float acc[4][4];
#pragma unroll
    for (int i = 0; i < 4; i++)
#pragma unroll
        for (int j = 0; j < 4; j++) acc[i][j] = 0.f;

    for (int tap = 0; tap < 9; tap++) {
        int dy = tap / 3, dx = tap % 3;
        int off[4];
#pragma unroll
        for (int j = 0; j < 4; j++) off[j] = (py[j] + dy) * 32 + (px[j] + dx);
        const float* wb = g_wt2 + tap * 65536 + oc0;
        for (int ict = 0; ict < 16; ict++) {
            int ic0 = ict * 16;
            float4 wv = *(const float4*)(wb + (ic0 + kk) * 256 + nn0);
            *(float4*)&Ws[kk][nn0] = wv;
            const float* ib = g_c1 + (size_t)b * 262144 + (size_t)(ic0 + kk) * HW;
#pragma unroll
            for (int j = 0; j < 4; j++) Is[kk][nn0 + j] = ib[off[j]];
            __syncthreads();
#pragma unroll
            for (int k2 = 0; k2 < 16; k2++) {
                float4 w4 = *(const float4*)&Ws[k2][ty * 4];
                float4 i4 = *(const float4*)&Is[k2][tx * 4];
                fma44(acc, w4, i4);
            }
            __syncthreads();
        }
    }
#pragma unroll
    for (int i = 0; i < 4; i++) {
        int oc = oc0 + ty * 4 + i;
        float bias = b2[oc];
#pragma unroll
        for (int j = 0; j < 4; j++) {
            int p = n0 + tx * 4 + j;
            if (p < 900) g_c2[(size_t)b * 230400 + (size_t)oc * 900 + p] = acc[i][j] + bias;
        }
    }
}

// ---------------- 3x3 stride-3 maxpool: 30x30 -> 10x10 ----------------
__global__ void k_pool() {
    int oc = blockIdx.x, b = blockIdx.y;
    int t = threadIdx.x;
    if (t >= 100) return;
    int y = t / 10, x = t % 10;
    const float* in = g_c2 + ((size_t)b * 256 + oc) * 900;
    float m = -3.4e38f;
#pragma unroll
    for (int dy = 0; dy < 3; dy++)
#pragma unroll
        for (int dx = 0; dx < 3; dx++)
            m = fmaxf(m, in[(3 * y + dy) * 30 + 3 * x + dx]);
    g_pool[((size_t)b * 256 + oc) * 100 + t] = m;
}

// ---------------- conv3 (3x3 VALID, 10x10 -> 8x8) + mean -> weight[b] ----------------
__global__ void k_conv3(const float* __restrict__ w3, const float* __restrict__ b3,
                        float* __restrict__ wout) {
    int b = blockIdx.x;
    int tid = threadIdx.x;
    int o = tid >> 2, part = tid & 3;         // 64 outputs x 4 partial sums
    int oy = o >> 3, ox = o & 7;
    float s = 0.f;
    for (int ic = part * 64; ic < part * 64 + 64; ic++) {
        const float* pp = g_pool + ((size_t)b * 256 + ic) * 100 + oy * 10 + ox;
        const float* wp = w3 + ic * 9;
#pragma unroll
        for (int ky = 0; ky < 3; ky++)
#pragma unroll
            for (int kx = 0; kx < 3; kx++)
                s = fmaf(pp[ky * 10 + kx], wp[ky * 3 + kx], s);
    }
    s += __shfl_down_sync(0xffffffffu, s, 1);
    s += __shfl_down_sync(0xffffffffu, s, 2);
    __shared__ float sh[64];
    if (part == 0) sh[o] = s;
    __syncthreads();
    if (tid < 32) {
        float v = sh[tid] + sh[tid + 32];
#pragma unroll
        for (int off = 16; off; off >>= 1) v += __shfl_xor_sync(0xffffffffu, v, off);
        if (tid == 0) wout[b] = v * (1.0f / 64.0f) + b3[0];
    }
}

// ---------------- launch ----------------
extern "C" void kernel_launch(void* const* d_in, const int* in_sizes, int n_in,
                              void* d_out, int out_size) {
    const float* fq_feats = (const float*)d_in[0];
    const float* fs_feats = (const float*)d_in[1];
    const float* f_q = (const float*)d_in[2];
    const float* f_s = (const float*)d_in[3];
    const float* w1 = (const float*)d_in[4];
    const float* b1 = (const float*)d_in[5];
    const float* w2 = (const float*)d_in[6];
    const float* b2 = (const float*)d_in[7];
    const float* w3 = (const float*)d_in[8];
    const float* b3 = (const float*)d_in[9];

    float* out     = (float*)d_out;
    float* fq_out  = out;                       // [4,512,32,32]
    float* att_out = out + 2097152;             // [4,512,32,32]
    float* w_out   = out + 4194304;             // [1,4]

    k_twt1<<<9216, 256>>>(w1);
    k_twt2<<<2304, 256>>>(w2);
    k_norms<<<dim3(4, 36, 2), 256>>>(fq_feats, fs_feats);
    k_corr<<<dim3(8, 8, 4), 256>>>(fq_feats, fs_feats);
    k_softmax<<<4096, 256>>>();
    k_att<<<dim3(16, 8, 4), 256>>>(f_s, att_out);
    k_norm2<<<dim3(4, 4, 2), 256>>>(f_q, att_out);
    k_fqout<<<2048, 256>>>(f_q, att_out, fq_out);
    k_conv1<<<dim3(16, 4, 4), 256>>>(f_q, f_s, b1);
    k_conv2<<<dim3(15, 4, 4), 256>>>(b2);
    k_pool<<<dim3(256, 4), 128>>>();
    k_conv3<<<4, 256>>>(w3, b3, w_out);
}

// round 4
// speedup vs baseline: 1.7917x; 1.2884x over previous
#include <cuda_runtime.h>
#include <cuda_bf16.h>

#define LL 9
#define BB 4
#define CC 512
#define HW 1024

// ---------------- scratch (device globals; no allocation) ----------------
__device__ __align__(16) float g_invq[LL*BB*HW];
__device__ __align__(16) float g_invs[LL*BB*HW];
__device__ __align__(16) float g_corr[(size_t)BB*HW*HW];   // 16 MB, reused as attn
__device__ __align__(16) float g_c1[BB*256*HW];            // conv1 out [b][256][32*32]
__device__ __align__(16) float g_c2[BB*256*900];           // conv2 out [b][256][30*30]
__device__ __align__(16) float g_pool[BB*256*100];         // pooled [b][256][10*10]
__device__ __align__(16) float g_wt1[9*1024*256];          // w1 transposed [tap][ic][oc]
__device__ __align__(16) float g_wt2[9*256*256];           // w2 transposed [tap][ic][oc]
__device__ __align__(16) float g_nq2[BB*HW];
__device__ __align__(16) float g_na2[BB*HW];

// ---------------- helpers ----------------
__device__ __forceinline__ void fma44(float (&acc)[4][4], float4 a, float4 b) {
    acc[0][0] = fmaf(a.x, b.x, acc[0][0]); acc[0][1] = fmaf(a.x, b.y, acc[0][1]);
    acc[0][2] = fmaf(a.x, b.z, acc[0][2]); acc[0][3] = fmaf(a.x, b.w, acc[0][3]);
    acc[1][0] = fmaf(a.y, b.x, acc[1][0]); acc[1][1] = fmaf(a.y, b.y, acc[1][1]);
    acc[1][2] = fmaf(a.y, b.z, acc[1][2]); acc[1][3] = fmaf(a.y, b.w, acc[1][3]);
    acc[2][0] = fmaf(a.z, b.x, acc[2][0]); acc[2][1] = fmaf(a.z, b.y, acc[2][1]);
    acc[2][2] = fmaf(a.z, b.z, acc[2][2]); acc[2][3] = fmaf(a.z, b.w, acc[2][3]);
    acc[3][0] = fmaf(a.w, b.x, acc[3][0]); acc[3][1] = fmaf(a.w, b.y, acc[3][1]);
    acc[3][2] = fmaf(a.w, b.z, acc[3][2]); acc[3][3] = fmaf(a.w, b.w, acc[3][3]);
}

__device__ __forceinline__ void ldsm4t(unsigned* r, unsigned addr) {
    asm volatile("ldmatrix.sync.aligned.m8n8.x4.trans.shared.b16 {%0,%1,%2,%3}, [%4];\n"
        : "=r"(r[0]), "=r"(r[1]), "=r"(r[2]), "=r"(r[3]) : "r"(addr));
}
__device__ __forceinline__ void mma_bf16(float* c, const unsigned* a, const unsigned* b) {
    asm volatile(
        "mma.sync.aligned.m16n8k16.row.col.f32.bf16.bf16.f32 "
        "{%0,%1,%2,%3}, {%4,%5,%6,%7}, {%8,%9}, {%0,%1,%2,%3};\n"
        : "+f"(c[0]), "+f"(c[1]), "+f"(c[2]), "+f"(c[3])
        : "r"(a[0]), "r"(a[1]), "r"(a[2]), "r"(a[3]), "r"(b[0]), "r"(b[1]));
}
// split float4 -> hi bf16x2 pair + lo bf16x2 pair (packed as unsigned)
__device__ __forceinline__ void cvt_hl(float4 v, unsigned& h0, unsigned& h1,
                                       unsigned& l0, unsigned& l1) {
    __nv_bfloat162 H0 = __floats2bfloat162_rn(v.x, v.y);
    __nv_bfloat162 H1 = __floats2bfloat162_rn(v.z, v.w);
    __nv_bfloat162 L0 = __floats2bfloat162_rn(v.x - __bfloat162float(H0.x),
                                              v.y - __bfloat162float(H0.y));
    __nv_bfloat162 L1 = __floats2bfloat162_rn(v.z - __bfloat162float(H1.x),
                                              v.w - __bfloat162float(H1.y));
    h0 = *(unsigned*)&H0; h1 = *(unsigned*)&H1;
    l0 = *(unsigned*)&L0; l1 = *(unsigned*)&L1;
}

// ---------------- weight transposes: w[oc][ic][tap] -> wt[tap][ic][oc] ----------------
__global__ void k_twt1(const float* __restrict__ w1) {
    int i = blockIdx.x * 256 + threadIdx.x;          // < 2359296
    float v = w1[i];
    int oc = i / 9216; int r = i % 9216; int ic = r / 9; int tap = r % 9;
    g_wt1[tap * 262144 + ic * 256 + oc] = v;
}
__global__ void k_twt2(const float* __restrict__ w2) {
    int i = blockIdx.x * 256 + threadIdx.x;          // < 589824
    float v = w2[i];
    int oc = i / 2304; int r = i % 2304; int ic = r / 9; int tap = r % 9;
    g_wt2[tap * 65536 + ic * 256 + oc] = v;
}

// ---------------- per-level per-pixel inverse channel norms ----------------
__global__ void k_norms(const float* __restrict__ fq, const float* __restrict__ fs) {
    int lb  = blockIdx.y;                             // 0..35 (l*B+b)
    int pix = blockIdx.x * 256 + threadIdx.x;         // 0..1023
    const float* src = (blockIdx.z == 0 ? fq : fs) + (size_t)lb * CC * HW + pix;
    float ss = 0.f;
#pragma unroll 8
    for (int c = 0; c < CC; c++) { float v = src[(size_t)c * HW]; ss = fmaf(v, v, ss); }
    float inv = 1.0f / fmaxf(sqrtf(ss), 1e-12f);
    (blockIdx.z == 0 ? g_invq : g_invs)[lb * HW + pix] = inv;
}

// ---------------- corr: g_corr = sum_l relu( (fq_l . fs_l) * invq * invs ) ----------------
// bf16-split tensor-core version: C = Ah*Bh + Ah*Bl + Al*Bh (fp32 accum).
// CTA 128x128 tile, 8 warps as 2(m)x4(n), warp = 64m x 32n, mma.m16n8k16.
// smem: [buf][Ah,Al,Bh,Bl][16 k][136 halves] (136-pad -> conflict-free ldmatrix.trans).
// Per-level epilogue: scale by invq*invs, ReLU, accumulate into L2-resident tile.
__global__ void __launch_bounds__(256, 2) k_corr(const float* __restrict__ fq,
                                                 const float* __restrict__ fs) {
    __shared__ __align__(16) unsigned smq[2][4][16][68];  // 68 u32 = 136 halves
    int b  = blockIdx.z;
    int m0 = blockIdx.y * 128, n0 = blockIdx.x * 128;
    int tid = threadIdx.x, lane = tid & 31, wid = tid >> 5;
    int wm = (wid >> 2) * 64, wn = (wid & 3) * 32;
    int kr = tid >> 4, mc = (tid & 15) * 8;           // loader: 16 k-rows x 8 floats

    // ldmatrix lane->address pieces (byte offsets inside one [16][136] array)
    int kA = (lane & 7) + ((lane >> 4) << 3);
    int cA = ((lane >> 3) & 1) << 3;
    int kB = (lane & 7) + (((lane >> 3) & 1) << 3);
    int cB = (lane >> 4) << 3;
    unsigned smbase = (unsigned)__cvta_generic_to_shared(&smq[0][0][0][0]);
    unsigned offA = (unsigned)(kA * 272 + (cA + wm) * 2);
    unsigned offB = (unsigned)(kB * 272 + (cB + wn) * 2);

    float* outp = g_corr + (size_t)b * HW * HW + (size_t)m0 * HW + n0;

    for (int l = 0; l < LL; l++) {
        const float* Ag = fq + (size_t)(l * BB + b) * CC * HW + m0;
        const float* Bg = fs + (size_t)(l * BB + b) * CC * HW + n0;

        float c[4][4][4];
#pragma unroll
        for (int f = 0; f < 4; f++)
#pragma unroll
            for (int g = 0; g < 4; g++) { c[f][g][0]=0.f; c[f][g][1]=0.f; c[f][g][2]=0.f; c[f][g][3]=0.f; }

        __syncthreads();                              // smem reuse across levels
        {   // prologue: k-tile 0 -> buf 0
            float4 a0g = *(const float4*)(Ag + (size_t)kr * HW + mc);
            float4 a1g = *(const float4*)(Ag + (size_t)kr * HW + mc + 4);
            float4 b0g = *(const float4*)(Bg + (size_t)kr * HW + mc);
            float4 b1g = *(const float4*)(Bg + (size_t)kr * HW + mc + 4);
            unsigned h0,h1,l0,l1;
            unsigned* pAh = &smq[0][0][kr][mc >> 1];
            unsigned* pAl = &smq[0][1][kr][mc >> 1];
            unsigned* pBh = &smq[0][2][kr][mc >> 1];
            unsigned* pBl = &smq[0][3][kr][mc >> 1];
            cvt_hl(a0g,h0,h1,l0,l1); pAh[0]=h0; pAh[1]=h1; pAl[0]=l0; pAl[1]=l1;
            cvt_hl(a1g,h0,h1,l0,l1); pAh[2]=h0; pAh[3]=h1; pAl[2]=l0; pAl[3]=l1;
            cvt_hl(b0g,h0,h1,l0,l1); pBh[0]=h0; pBh[1]=h1; pBl[0]=l0; pBl[1]=l1;
            cvt_hl(b1g,h0,h1,l0,l1); pBh[2]=h0; pBh[3]=h1; pBl[2]=l0; pBl[3]=l1;
        }
        __syncthreads();

        int buf = 0;
        for (int kt = 0; kt < 32; kt++) {
            float4 a0g, a1g, b0g, b1g;
            if (kt < 31) {
                int k0 = (kt + 1) * 16;
                a0g = *(const float4*)(Ag + (size_t)(k0 + kr) * HW + mc);
                a1g = *(const float4*)(Ag + (size_t)(k0 + kr) * HW + mc + 4);
                b0g = *(const float4*)(Bg + (size_t)(k0 + kr) * HW + mc);
                b1g = *(const float4*)(Bg + (size_t)(k0 + kr) * HW + mc + 4);
            }
            unsigned base = smbase + (unsigned)buf * 17408u;
            unsigned a[16], bh[8], bl[8];
#pragma unroll
            for (int f = 0; f < 4; f++) ldsm4t(a + 4 * f, base + offA + f * 32);
#pragma unroll
            for (int g2 = 0; g2 < 2; g2++) ldsm4t(bh + 4 * g2, base + 2u * 4352u + offB + g2 * 32);
#pragma unroll
            for (int g2 = 0; g2 < 2; g2++) ldsm4t(bl + 4 * g2, base + 3u * 4352u + offB + g2 * 32);
#pragma unroll
            for (int f = 0; f < 4; f++)
#pragma unroll
                for (int g = 0; g < 4; g++) {
                    mma_bf16(c[f][g], a + 4 * f, bh + 2 * g);
                    mma_bf16(c[f][g], a + 4 * f, bl + 2 * g);
                }
#pragma unroll
            for (int f = 0; f < 4; f++) ldsm4t(a + 4 * f, base + 4352u + offA + f * 32);
#pragma unroll
            for (int f = 0; f < 4; f++)
#pragma unroll
                for (int g = 0; g < 4; g++)
                    mma_bf16(c[f][g], a + 4 * f, bh + 2 * g);

            if (kt < 31) {
                int nb = buf ^ 1;
                unsigned h0,h1,l0,l1;
                unsigned* pAh = &smq[nb][0][kr][mc >> 1];
                unsigned* pAl = &smq[nb][1][kr][mc >> 1];
                unsigned* pBh = &smq[nb][2][kr][mc >> 1];
                unsigned* pBl = &smq[nb][3][kr][mc >> 1];
                cvt_hl(a0g,h0,h1,l0,l1); pAh[0]=h0; pAh[1]=h1; pAl[0]=l0; pAl[1]=l1;
                cvt_hl(a1g,h0,h1,l0,l1); pAh[2]=h0; pAh[3]=h1; pAl[2]=l0; pAl[3]=l1;
                cvt_hl(b0g,h0,h1,l0,l1); pBh[0]=h0; pBh[1]=h1; pBl[0]=l0; pBl[1]=l1;
                cvt_hl(b1g,h0,h1,l0,l1); pBh[2]=h0; pBh[3]=h1; pBl[2]=l0; pBl[3]=l1;
                __syncthreads();
                buf = nb;
            }
        }

        // per-level epilogue: scale, relu, accumulate into global tile (L2-resident)
        const float* iq = g_invq + (l * BB + b) * HW + m0;
        const float* is = g_invs + (l * BB + b) * HW + n0;
#pragma unroll
        for (int f = 0; f < 4; f++) {
            int r0 = wm + f * 16 + (lane >> 2), r1 = r0 + 8;
            float q0 = iq[r0], q1 = iq[r1];
#pragma unroll
            for (int g = 0; g < 4; g++) {
                int cb = wn + g * 8 + (lane & 3) * 2;
                float s0 = is[cb], s1 = is[cb + 1];
                float v00 = fmaxf(c[f][g][0] * q0 * s0, 0.f);
                float v01 = fmaxf(c[f][g][1] * q0 * s1, 0.f);
                float v10 = fmaxf(c[f][g][2] * q1 * s0, 0.f);
                float v11 = fmaxf(c[f][g][3] * q1 * s1, 0.f);
                float2* p0 = (float2*)(outp + (size_t)r0 * HW + cb);
                float2* p1 = (float2*)(outp + (size_t)r1 * HW + cb);
                if (l == 0) {
                    *p0 = make_float2(v00, v01);
                    *p1 = make_float2(v10, v11);
                } else {
                    float2 o0 = *p0, o1 = *p1;
                    o0.x += v00; o0.y += v01; o1.x += v10; o1.y += v11;
                    *p0 = o0; *p1 = o1;
                }
            }
        }
    }
}

// ---------------- row softmax (scale = TEMP/L folds the mean) ----------------
__global__ void k_softmax() {
    float* r = g_corr + (size_t)blockIdx.x * HW;      // blockIdx.x = b*1024 + q
    int tid = threadIdx.x, wid = tid >> 5, lane = tid & 31;
    const float sc = 20.0f / 9.0f;
    float4 v = ((const float4*)r)[tid];
    v.x *= sc; v.y *= sc; v.z *= sc; v.w *= sc;
    float mx = fmaxf(fmaxf(v.x, v.y), fmaxf(v.z, v.w));
#pragma unroll
    for (int o = 16; o; o >>= 1) mx = fmaxf(mx, __shfl_xor_sync(0xffffffffu, mx, o));
    __shared__ float sh[8];
    if (lane == 0) sh[wid] = mx;
    __syncthreads();
    float m = sh[0];
#pragma unroll
    for (int k = 1; k < 8; k++) m = fmaxf(m, sh[k]);
    v.x = __expf(v.x - m); v.y = __expf(v.y - m);
    v.z = __expf(v.z - m); v.w = __expf(v.w - m);
    float s = v.x + v.y + v.z + v.w;
#pragma unroll
    for (int o = 16; o; o >>= 1) s += __shfl_xor_sync(0xffffffffu, s, o);
    __syncthreads();
    if (lane == 0) sh[wid] = s;
    __syncthreads();
    float tot = 0.f;
#pragma unroll
    for (int k = 0; k < 8; k++) tot += sh[k];
    float inv = 1.0f / tot;
    v.x *= inv; v.y *= inv; v.z *= inv; v.w *= inv;
    ((float4*)r)[tid] = v;
}

// ---------------- att_fq[b,c,q] = sum_s attn[b,q,s] * f_s[b,c,s]  (NT gemm) ----------------
__global__ void k_att(const float* __restrict__ fs_in, float* __restrict__ attout) {
    __shared__ __align__(16) float As[16][68];
    __shared__ __align__(16) float Bs[16][68];
    int b  = blockIdx.z;
    int m0 = blockIdx.y * 64;   // c
    int n0 = blockIdx.x * 64;   // q
    int tid = threadIdx.x, tx = tid & 15, ty = tid >> 4;
    int lm = tid >> 2, lk = (tid & 3) * 4;            // 64 rows, 4 k each

    const float* A  = fs_in + (size_t)b * CC * HW;    // [512][1024] (k=s contig)
    const float* Bm = g_corr + (size_t)b * HW * HW;   // attn [1024][1024] (k=s contig)

    float acc[4][4];
#pragma unroll
    for (int i = 0; i < 4; i++)
#pragma unroll
        for (int j = 0; j < 4; j++) acc[i][j] = 0.f;

    for (int kt = 0; kt < 64; kt++) {
        int k0 = kt * 16;
        float4 a4 = *(const float4*)(A  + (size_t)(m0 + lm) * HW + k0 + lk);
        float4 b4 = *(const float4*)(Bm + (size_t)(n0 + lm) * HW + k0 + lk);
        As[lk + 0][lm] = a4.x; As[lk + 1][lm] = a4.y; As[lk + 2][lm] = a4.z; As[lk + 3][lm] = a4.w;
        Bs[lk + 0][lm] = b4.x; Bs[lk + 1][lm] = b4.y; Bs[lk + 2][lm] = b4.z; Bs[lk + 3][lm] = b4.w;
        __syncthreads();
#pragma unroll
        for (int k2 = 0; k2 < 16; k2++) {
            float4 av = *(const float4*)&As[k2][ty * 4];
            float4 bv = *(const float4*)&Bs[k2][tx * 4];
            fma44(acc, av, bv);
        }
        __syncthreads();
    }
    float* outp = attout + (size_t)b * CC * HW + (size_t)m0 * HW + n0;
#pragma unroll
    for (int i = 0; i < 4; i++) {
        float4 o = make_float4(acc[i][0], acc[i][1], acc[i][2], acc[i][3]);
        *(float4*)(outp + (size_t)(ty * 4 + i) * HW + tx * 4) = o;
    }
}

// ---------------- inverse channel norms of f_q and att_fq ----------------
__global__ void k_norm2(const float* __restrict__ f_q, const float* __restrict__ att) {
    int b   = blockIdx.y;
    int pix = blockIdx.x * 256 + threadIdx.x;
    const float* src = (blockIdx.z == 0 ? f_q : att) + (size_t)b * CC * HW + pix;
    float ss = 0.f;
#pragma unroll 8
    for (int c = 0; c < CC; c++) { float v = src[(size_t)c * HW]; ss = fmaf(v, v, ss); }
    float inv = 1.0f / fmaxf(sqrtf(ss), 1e-12f);
    (blockIdx.z == 0 ? g_nq2 : g_na2)[b * HW + pix] = inv;
}

// ---------------- fq = l2n(f_q) + 0.5*l2n(att_fq) ----------------
__global__ void k_fqout(const float* __restrict__ f_q, const float* __restrict__ att,
                        float* __restrict__ fqo) {
    int i4 = blockIdx.x * 256 + threadIdx.x;          // < 524288
    int base = i4 * 4;
    int b = base >> 19;
    int pix = base & 1023;
    float4 q = ((const float4*)f_q)[i4];
    float4 a = ((const float4*)att)[i4];
    int ni = (b * HW + pix) >> 2;
    float4 nq = ((const float4*)g_nq2)[ni];
    float4 na = ((const float4*)g_na2)[ni];
    float4 o;
    o.x = q.x * nq.x + a.x * na.x * 0.5f;
    o.y = q.y * nq.y + a.y * na.y * 0.5f;
    o.z = q.z * nq.z + a.z * na.z * 0.5f;
    o.w = q.w * nq.w + a.w * na.w * 0.5f;
    ((float4*)fqo)[i4] = o;
}

// ---------------- conv1: implicit GEMM, input concat(f_q,f_s), dil=2, pad=2, +bias, relu ----------------
__global__ void k_conv1(const float* __restrict__ f_q, const float* __restrict__ f_s,
                        const float* __restrict__ b1) {
    __shared__ __align__(16) float Ws[16][64];
    __shared__ __align__(16) float Is[16][64];
    int b = blockIdx.z, oc0 = blockIdx.y * 64, n0 = blockIdx.x * 64;
    int tid = threadIdx.x, tx = tid & 15, ty = tid >> 4;
    int kk = (tid * 4) >> 6, nn0 = (tid * 4) & 63;
    const float* fqp = f_q + (size_t)b * CC * HW;
    const float* fsp = f_s + (size_t)b * CC * HW;

    int py[4], px[4];
#pragma unroll
    for (int j = 0; j < 4; j++) { int p = n0 + nn0 + j; py[j] = p >> 5; px[j] = p & 31; }

    float acc[4][4];
#pragma unroll
    for (int i = 0; i < 4; i++)
#pragma unroll
        for (int j = 0; j < 4; j++) acc[i][j] = 0.f;

    for (int tap = 0; tap < 9; tap++) {
        int dy = 2 * (tap / 3) - 2, dx = 2 * (tap % 3) - 2;
        int off[4]; bool inb[4];
#pragma unroll
        for (int j = 0; j < 4; j++) {
            int iy = py[j] + dy, ix = px[j] + dx;
            inb[j] = ((unsigned)iy < 32u) && ((unsigned)ix < 32u);
            off[j] = iy * 32 + ix;
        }
        const float* wb = g_wt1 + tap * 262144 + oc0;
        for (int ict = 0; ict < 64; ict++) {
            int ic0 = ict * 16;
            float4 wv = *(const float4*)(wb + (ic0 + kk) * 256 + nn0);
            *(float4*)&Ws[kk][nn0] = wv;
            const float* ib = (ic0 < 512 ? fqp + (size_t)ic0 * HW
                                         : fsp + (size_t)(ic0 - 512) * HW) + (size_t)kk * HW;
#pragma unroll
            for (int j = 0; j < 4; j++) Is[kk][nn0 + j] = inb[j] ? ib[off[j]] : 0.f;
            __syncthreads();
#pragma unroll
            for (int k2 = 0; k2 < 16; k2++) {
                float4 w4 = *(const float4*)&Ws[k2][ty * 4];
                float4 i4 = *(const float4*)&Is[k2][tx * 4];
                fma44(acc, w4, i4);
            }
            __syncthreads();
        }
    }
    float* outp = g_c1 + (size_t)b * 262144;
#pragma unroll
    for (int i = 0; i < 4; i++) {
        int oc = oc0 + ty * 4 + i;
        float bias = b1[oc];
        float4 o = make_float4(fmaxf(acc[i][0] + bias, 0.f), fmaxf(acc[i][1] + bias, 0.f),
                               fmaxf(acc[i][2] + bias, 0.f), fmaxf(acc[i][3] + bias, 0.f));
        *(float4*)(outp + (size_t)oc * HW + n0 + tx * 4) = o;
    }
}

// ---------------- conv2: implicit GEMM, 3x3 VALID on 32x32 -> 30x30, +bias ----------------
__global__ void k_conv2(const float* __restrict__ b2) {
    __shared__ __align__(16) float Ws[16][64];
    __shared__ __align__(16) float Is[16][64];
    int b = blockIdx.z, oc0 = blockIdx.y * 64, n0 = blockIdx.x * 64;
    int tid = threadIdx.x, tx = tid & 15, ty = tid >> 4;
    int kk = (tid * 4) >> 6, nn0 = (tid * 4) & 63;

    int py[4], px[4];
#pragma unroll
    for (int j = 0; j < 4; j++) {
        int p = n0 + nn0 + j; if (p > 899) p = 899;
        py[j] = p / 30; px[j] = p % 30;
    }

    float acc[4][4];
#pragma unroll
    for (int i = 0; i < 4; i++)
#pragma unroll
        for (int j = 0; j < 4; j++) acc[i][j] = 0.f;

    for (int tap = 0; tap < 9; tap++) {
        int dy = tap / 3, dx = tap % 3;
        int off[4];
#pragma unroll
        for (int j = 0; j < 4; j++) off[j] = (py[j] + dy) * 32 + (px[j] + dx);
        const float* wb = g_wt2 + tap * 65536 + oc0;
        for (int ict = 0; ict < 16; ict++) {
            int ic0 = ict * 16;
            float4 wv = *(const float4*)(wb + (ic0 + kk) * 256 + nn0);
            *(float4*)&Ws[kk][nn0] = wv;
            const float* ib = g_c1 + (size_t)b * 262144 + (size_t)(ic0 + kk) * HW;
#pragma unroll
            for (int j = 0; j < 4; j++) Is[kk][nn0 + j] = ib[off[j]];
            __syncthreads();
#pragma unroll
            for (int k2 = 0; k2 < 16; k2++) {
                float4 w4 = *(const float4*)&Ws[k2][ty * 4];
                float4 i4 = *(const float4*)&Is[k2][tx * 4];
                fma44(acc, w4, i4);
            }
            __syncthreads();
        }
    }
#pragma unroll
    for (int i = 0; i < 4; i++) {
        int oc = oc0 + ty * 4 + i;
        float bias = b2[oc];
#pragma unroll
        for (int j = 0; j < 4; j++) {
            int p = n0 + tx * 4 + j;
            if (p < 900) g_c2[(size_t)b * 230400 + (size_t)oc * 900 + p] = acc[i][j] + bias;
        }
    }
}

// ---------------- 3x3 stride-3 maxpool: 30x30 -> 10x10 ----------------
__global__ void k_pool() {
    int oc = blockIdx.x, b = blockIdx.y;
    int t = threadIdx.x;
    if (t >= 100) return;
    int y = t / 10, x = t % 10;
    const float* in = g_c2 + ((size_t)b * 256 + oc) * 900;
    float m = -3.4e38f;
#pragma unroll
    for (int dy = 0; dy < 3; dy++)
#pragma unroll
        for (int dx = 0; dx < 3; dx++)
            m = fmaxf(m, in[(3 * y + dy) * 30 + 3 * x + dx]);
    g_pool[((size_t)b * 256 + oc) * 100 + t] = m;
}

// ---------------- conv3 (3x3 VALID, 10x10 -> 8x8) + mean -> weight[b] ----------------
__global__ void k_conv3(const float* __restrict__ w3, const float* __restrict__ b3,
                        float* __restrict__ wout) {
    int b = blockIdx.x;
    int tid = threadIdx.x;
    int o = tid >> 2, part = tid & 3;         // 64 outputs x 4 partial sums
    int oy = o >> 3, ox = o & 7;
    float s = 0.f;
    for (int ic = part * 64; ic < part * 64 + 64; ic++) {
        const float* pp = g_pool + ((size_t)b * 256 + ic) * 100 + oy * 10 + ox;
        const float* wp = w3 + ic * 9;
#pragma unroll
        for (int ky = 0; ky < 3; ky++)
#pragma unroll
            for (int kx = 0; kx < 3; kx++)
                s = fmaf(pp[ky * 10 + kx], wp[ky * 3 + kx], s);
    }
    s += __shfl_down_sync(0xffffffffu, s, 1);
    s += __shfl_down_sync(0xffffffffu, s, 2);
    __shared__ float sh[64];
    if (part == 0) sh[o] = s;
    __syncthreads();
    if (tid < 32) {
        float v = sh[tid] + sh[tid + 32];
#pragma unroll
        for (int off = 16; off; off >>= 1) v += __shfl_xor_sync(0xffffffffu, v, off);
        if (tid == 0) wout[b] = v * (1.0f / 64.0f) + b3[0];
    }
}

// ---------------- launch ----------------
extern "C" void kernel_launch(void* const* d_in, const int* in_sizes, int n_in,
                              void* d_out, int out_size) {
    const float* fq_feats = (const float*)d_in[0];
    const float* fs_feats = (const float*)d_in[1];
    const float* f_q = (const float*)d_in[2];
    const float* f_s = (const float*)d_in[3];
    const float* w1 = (const float*)d_in[4];
    const float* b1 = (const float*)d_in[5];
    const float* w2 = (const float*)d_in[6];
    const float* b2 = (const float*)d_in[7];
    const float* w3 = (const float*)d_in[8];
    const float* b3 = (const float*)d_in[9];

    float* out     = (float*)d_out;
    float* fq_out  = out;                       // [4,512,32,32]
    float* att_out = out + 2097152;             // [4,512,32,32]
    float* w_out   = out + 4194304;             // [1,4]

    k_twt1<<<9216, 256>>>(w1);
    k_twt2<<<2304, 256>>>(w2);
    k_norms<<<dim3(4, 36, 2), 256>>>(fq_feats, fs_feats);
    k_corr<<<dim3(8, 8, 4), 256>>>(fq_feats, fs_feats);
    k_softmax<<<4096, 256>>>();
    k_att<<<dim3(16, 8, 4), 256>>>(f_s, att_out);
    k_norm2<<<dim3(4, 4, 2), 256>>>(f_q, att_out);
    k_fqout<<<2048, 256>>>(f_q, att_out, fq_out);
    k_conv1<<<dim3(16, 4, 4), 256>>>(f_q, f_s, b1);
    k_conv2<<<dim3(15, 4, 4), 256>>>(b2);
    k_pool<<<dim3(256, 4), 128>>>();
    k_conv3<<<4, 256>>>(w3, b3, w_out);
}

// round 6
// speedup vs baseline: 2.1974x; 1.2265x over previous
#include <cuda_runtime.h>
#include <cuda_bf16.h>

#define LL 9
#define BB 4
#define CC 512
#define HW 1024

// ---------------- scratch (device globals; no allocation) ----------------
__device__ __align__(16) float g_invq[LL*BB*HW];
__device__ __align__(16) float g_invs[LL*BB*HW];
__device__ __align__(16) float g_corr[(size_t)BB*HW*HW];   // 16 MB, reused as attn
__device__ __align__(16) float g_c1[BB*256*HW];            // conv1 out [b][256][32*32]
__device__ __align__(16) float g_c2[BB*256*900];           // conv2 out [b][256][30*30]
__device__ __align__(16) float g_pool[BB*256*100];         // pooled [b][256][10*10]
__device__ __align__(16) __nv_bfloat16 g_wt1h[9*1024*256]; // w1 hi [tap][ic][oc]
__device__ __align__(16) __nv_bfloat16 g_wt1l[9*1024*256]; // w1 lo [tap][ic][oc]
__device__ __align__(16) float g_wt2[9*256*256];           // w2 transposed [tap][ic][oc]
__device__ __align__(16) float g_nq2[BB*HW];
__device__ __align__(16) float g_na2[BB*HW];

// ---------------- helpers ----------------
__device__ __forceinline__ void fma44(float (&acc)[4][4], float4 a, float4 b) {
    acc[0][0] = fmaf(a.x, b.x, acc[0][0]); acc[0][1] = fmaf(a.x, b.y, acc[0][1]);
    acc[0][2] = fmaf(a.x, b.z, acc[0][2]); acc[0][3] = fmaf(a.x, b.w, acc[0][3]);
    acc[1][0] = fmaf(a.y, b.x, acc[1][0]); acc[1][1] = fmaf(a.y, b.y, acc[1][1]);
    acc[1][2] = fmaf(a.y, b.z, acc[1][2]); acc[1][3] = fmaf(a.y, b.w, acc[1][3]);
    acc[2][0] = fmaf(a.z, b.x, acc[2][0]); acc[2][1] = fmaf(a.z, b.y, acc[2][1]);
    acc[2][2] = fmaf(a.z, b.z, acc[2][2]); acc[2][3] = fmaf(a.z, b.w, acc[2][3]);
    acc[3][0] = fmaf(a.w, b.x, acc[3][0]); acc[3][1] = fmaf(a.w, b.y, acc[3][1]);
    acc[3][2] = fmaf(a.w, b.z, acc[3][2]); acc[3][3] = fmaf(a.w, b.w, acc[3][3]);
}

__device__ __forceinline__ void ldsm4t(unsigned* r, unsigned addr) {
    asm volatile("ldmatrix.sync.aligned.m8n8.x4.trans.shared.b16 {%0,%1,%2,%3}, [%4];\n"
        : "=r"(r[0]), "=r"(r[1]), "=r"(r[2]), "=r"(r[3]) : "r"(addr));
}
__device__ __forceinline__ void mma_bf16(float* c, const unsigned* a, const unsigned* b) {
    asm volatile(
        "mma.sync.aligned.m16n8k16.row.col.f32.bf16.bf16.f32 "
        "{%0,%1,%2,%3}, {%4,%5,%6,%7}, {%8,%9}, {%0,%1,%2,%3};\n"
        : "+f"(c[0]), "+f"(c[1]), "+f"(c[2]), "+f"(c[3])
        : "r"(a[0]), "r"(a[1]), "r"(a[2]), "r"(a[3]), "r"(b[0]), "r"(b[1]));
}
// split float4 -> hi bf16x2 pair + lo bf16x2 pair (packed as unsigned)
__device__ __forceinline__ void cvt_hl(float4 v, unsigned& h0, unsigned& h1,
                                       unsigned& l0, unsigned& l1) {
    __nv_bfloat162 H0 = __floats2bfloat162_rn(v.x, v.y);
    __nv_bfloat162 H1 = __floats2bfloat162_rn(v.z, v.w);
    __nv_bfloat162 L0 = __floats2bfloat162_rn(v.x - __bfloat162float(H0.x),
                                              v.y - __bfloat162float(H0.y));
    __nv_bfloat162 L1 = __floats2bfloat162_rn(v.z - __bfloat162float(H1.x),
                                              v.w - __bfloat162float(H1.y));
    h0 = *(unsigned*)&H0; h1 = *(unsigned*)&H1;
    l0 = *(unsigned*)&L0; l1 = *(unsigned*)&L1;
}

// ---------------- weight prep ----------------
// w1[oc][ic][tap] -> bf16 hi/lo [tap][ic][oc]
__global__ void k_twt1(const float* __restrict__ w1) {
    int i = blockIdx.x * 256 + threadIdx.x;          // < 2359296
    float v = w1[i];
    int oc = i / 9216; int r = i % 9216; int ic = r / 9; int tap = r % 9;
    __nv_bfloat16 h = __float2bfloat16(v);
    __nv_bfloat16 lo = __float2bfloat16(v - __bfloat162float(h));
    int o = tap * 262144 + ic * 256 + oc;
    g_wt1h[o] = h; g_wt1l[o] = lo;
}
__global__ void k_twt2(const float* __restrict__ w2) {
    int i = blockIdx.x * 256 + threadIdx.x;          // < 589824
    float v = w2[i];
    int oc = i / 2304; int r = i % 2304; int ic = r / 9; int tap = r % 9;
    g_wt2[tap * 65536 + ic * 256 + oc] = v;
}

// ---------------- per-level per-pixel inverse channel norms ----------------
__global__ void k_norms(const float* __restrict__ fq, const float* __restrict__ fs) {
    int lb  = blockIdx.y;                             // 0..35 (l*B+b)
    int pix = blockIdx.x * 256 + threadIdx.x;         // 0..1023
    const float* src = (blockIdx.z == 0 ? fq : fs) + (size_t)lb * CC * HW + pix;
    float ss = 0.f;
#pragma unroll 8
    for (int c = 0; c < CC; c++) { float v = src[(size_t)c * HW]; ss = fmaf(v, v, ss); }
    float inv = 1.0f / fmaxf(sqrtf(ss), 1e-12f);
    (blockIdx.z == 0 ? g_invq : g_invs)[lb * HW + pix] = inv;
}

// ---------------- corr: bf16-split tensor-core (proven R4 version) ----------------
__global__ void __launch_bounds__(256, 2) k_corr(const float* __restrict__ fq,
                                                 const float* __restrict__ fs) {
    __shared__ __align__(16) unsigned smq[2][4][16][68];  // 68 u32 = 136 halves
    int b  = blockIdx.z;
    int m0 = blockIdx.y * 128, n0 = blockIdx.x * 128;
    int tid = threadIdx.x, lane = tid & 31, wid = tid >> 5;
    int wm = (wid >> 2) * 64, wn = (wid & 3) * 32;
    int kr = tid >> 4, mc = (tid & 15) * 8;           // loader: 16 k-rows x 8 floats

    int kA = (lane & 7) + ((lane >> 4) << 3);
    int cA = ((lane >> 3) & 1) << 3;
    int kB = (lane & 7) + (((lane >> 3) & 1) << 3);
    int cB = (lane >> 4) << 3;
    unsigned smbase = (unsigned)__cvta_generic_to_shared(&smq[0][0][0][0]);
    unsigned offA = (unsigned)(kA * 272 + (cA + wm) * 2);
    unsigned offB = (unsigned)(kB * 272 + (cB + wn) * 2);

    float* outp = g_corr + (size_t)b * HW * HW + (size_t)m0 * HW + n0;

    for (int l = 0; l < LL; l++) {
        const float* Ag = fq + (size_t)(l * BB + b) * CC * HW + m0;
        const float* Bg = fs + (size_t)(l * BB + b) * CC * HW + n0;

        float c[4][4][4];
#pragma unroll
        for (int f = 0; f < 4; f++)
#pragma unroll
            for (int g = 0; g < 4; g++) { c[f][g][0]=0.f; c[f][g][1]=0.f; c[f][g][2]=0.f; c[f][g][3]=0.f; }

        __syncthreads();                              // smem reuse across levels
        {   // prologue: k-tile 0 -> buf 0
            float4 a0g = *(const float4*)(Ag + (size_t)kr * HW + mc);
            float4 a1g = *(const float4*)(Ag + (size_t)kr * HW + mc + 4);
            float4 b0g = *(const float4*)(Bg + (size_t)kr * HW + mc);
            float4 b1g = *(const float4*)(Bg + (size_t)kr * HW + mc + 4);
            unsigned h0,h1,l0,l1;
            unsigned* pAh = &smq[0][0][kr][mc >> 1];
            unsigned* pAl = &smq[0][1][kr][mc >> 1];
            unsigned* pBh = &smq[0][2][kr][mc >> 1];
            unsigned* pBl = &smq[0][3][kr][mc >> 1];
            cvt_hl(a0g,h0,h1,l0,l1); pAh[0]=h0; pAh[1]=h1; pAl[0]=l0; pAl[1]=l1;
            cvt_hl(a1g,h0,h1,l0,l1); pAh[2]=h0; pAh[3]=h1; pAl[2]=l0; pAl[3]=l1;
            cvt_hl(b0g,h0,h1,l0,l1); pBh[0]=h0; pBh[1]=h1; pBl[0]=l0; pBl[1]=l1;
            cvt_hl(b1g,h0,h1,l0,l1); pBh[2]=h0; pBh[3]=h1; pBl[2]=l0; pBl[3]=l1;
        }
        __syncthreads();

        int buf = 0;
        for (int kt = 0; kt < 32; kt++) {
            float4 a0g, a1g, b0g, b1g;
            if (kt < 31) {
                int k0 = (kt + 1) * 16;
                a0g = *(const float4*)(Ag + (size_t)(k0 + kr) * HW + mc);
                a1g = *(const float4*)(Ag + (size_t)(k0 + kr) * HW + mc + 4);
                b0g = *(const float4*)(Bg + (size_t)(k0 + kr) * HW + mc);
                b1g = *(const float4*)(Bg + (size_t)(k0 + kr) * HW + mc + 4);
            }
            unsigned base = smbase + (unsigned)buf * 17408u;
            unsigned a[16], bh[8], bl[8];
#pragma unroll
            for (int f = 0; f < 4; f++) ldsm4t(a + 4 * f, base + offA + f * 32);
#pragma unroll
            for (int g2 = 0; g2 < 2; g2++) ldsm4t(bh + 4 * g2, base + 2u * 4352u + offB + g2 * 32);
#pragma unroll
            for (int g2 = 0; g2 < 2; g2++) ldsm4t(bl + 4 * g2, base + 3u * 4352u + offB + g2 * 32);
#pragma unroll
            for (int f = 0; f < 4; f++)
#pragma unroll
                for (int g = 0; g < 4; g++) {
                    mma_bf16(c[f][g], a + 4 * f, bh + 2 * g);
                    mma_bf16(c[f][g], a + 4 * f, bl + 2 * g);
                }
#pragma unroll
            for (int f = 0; f < 4; f++) ldsm4t(a + 4 * f, base + 4352u + offA + f * 32);
#pragma unroll
            for (int f = 0; f < 4; f++)
#pragma unroll
                for (int g = 0; g < 4; g++)
                    mma_bf16(c[f][g], a + 4 * f, bh + 2 * g);

            if (kt < 31) {
                int nb = buf ^ 1;
                unsigned h0,h1,l0,l1;
                unsigned* pAh = &smq[nb][0][kr][mc >> 1];
                unsigned* pAl = &smq[nb][1][kr][mc >> 1];
                unsigned* pBh = &smq[nb][2][kr][mc >> 1];
                unsigned* pBl = &smq[nb][3][kr][mc >> 1];
                cvt_hl(a0g,h0,h1,l0,l1); pAh[0]=h0; pAh[1]=h1; pAl[0]=l0; pAl[1]=l1;
                cvt_hl(a1g,h0,h1,l0,l1); pAh[2]=h0; pAh[3]=h1; pAl[2]=l0; pAl[3]=l1;
                cvt_hl(b0g,h0,h1,l0,l1); pBh[0]=h0; pBh[1]=h1; pBl[0]=l0; pBl[1]=l1;
                cvt_hl(b1g,h0,h1,l0,l1); pBh[2]=h0; pBh[3]=h1; pBl[2]=l0; pBl[3]=l1;
                __syncthreads();
                buf = nb;
            }
        }

        const float* iq = g_invq + (l * BB + b) * HW + m0;
        const float* is = g_invs + (l * BB + b) * HW + n0;
#pragma unroll
        for (int f = 0; f < 4; f++) {
            int r0 = wm + f * 16 + (lane >> 2), r1 = r0 + 8;
            float q0 = iq[r0], q1 = iq[r1];
#pragma unroll
            for (int g = 0; g < 4; g++) {
                int cb = wn + g * 8 + (lane & 3) * 2;
                float s0 = is[cb], s1 = is[cb + 1];
                float v00 = fmaxf(c[f][g][0] * q0 * s0, 0.f);
                float v01 = fmaxf(c[f][g][1] * q0 * s1, 0.f);
                float v10 = fmaxf(c[f][g][2] * q1 * s0, 0.f);
                float v11 = fmaxf(c[f][g][3] * q1 * s1, 0.f);
                float2* p0 = (float2*)(outp + (size_t)r0 * HW + cb);
                float2* p1 = (float2*)(outp + (size_t)r1 * HW + cb);
                if (l == 0) {
                    *p0 = make_float2(v00, v01);
                    *p1 = make_float2(v10, v11);
                } else {
                    float2 o0 = *p0, o1 = *p1;
                    o0.x += v00; o0.y += v01; o1.x += v10; o1.y += v11;
                    *p0 = o0; *p1 = o1;
                }
            }
        }
    }
}

// ---------------- row softmax (scale = TEMP/L folds the mean) ----------------
__global__ void k_softmax() {
    float* r = g_corr + (size_t)blockIdx.x * HW;      // blockIdx.x = b*1024 + q
    int tid = threadIdx.x, wid = tid >> 5, lane = tid & 31;
    const float sc = 20.0f / 9.0f;
    float4 v = ((const float4*)r)[tid];
    v.x *= sc; v.y *= sc; v.z *= sc; v.w *= sc;
    float mx = fmaxf(fmaxf(v.x, v.y), fmaxf(v.z, v.w));
#pragma unroll
    for (int o = 16; o; o >>= 1) mx = fmaxf(mx, __shfl_xor_sync(0xffffffffu, mx, o));
    __shared__ float sh[8];
    if (lane == 0) sh[wid] = mx;
    __syncthreads();
    float m = sh[0];
#pragma unroll
    for (int k = 1; k < 8; k++) m = fmaxf(m, sh[k]);
    v.x = __expf(v.x - m); v.y = __expf(v.y - m);
    v.z = __expf(v.z - m); v.w = __expf(v.w - m);
    float s = v.x + v.y + v.z + v.w;
#pragma unroll
    for (int o = 16; o; o >>= 1) s += __shfl_xor_sync(0xffffffffu, s, o);
    __syncthreads();
    if (lane == 0) sh[wid] = s;
    __syncthreads();
    float tot = 0.f;
#pragma unroll
    for (int k = 0; k < 8; k++) tot += sh[k];
    float inv = 1.0f / tot;
    v.x *= inv; v.y *= inv; v.z *= inv; v.w *= inv;
    ((float4*)r)[tid] = v;
}

// ---------------- att_fq[b,c,q] = sum_s attn[b,q,s] * f_s[b,c,s]  (NT gemm) ----------------
__global__ void k_att(const float* __restrict__ fs_in, float* __restrict__ attout) {
    __shared__ __align__(16) float As[16][68];
    __shared__ __align__(16) float Bs[16][68];
    int b  = blockIdx.z;
    int m0 = blockIdx.y * 64;   // c
    int n0 = blockIdx.x * 64;   // q
    int tid = threadIdx.x, tx = tid & 15, ty = tid >> 4;
    int lm = tid >> 2, lk = (tid & 3) * 4;            // 64 rows, 4 k each

    const float* A  = fs_in + (size_t)b * CC * HW;    // [512][1024] (k=s contig)
    const float* Bm = g_corr + (size_t)b * HW * HW;   // attn [1024][1024] (k=s contig)

    float acc[4][4];
#pragma unroll
    for (int i = 0; i < 4; i++)
#pragma unroll
        for (int j = 0; j < 4; j++) acc[i][j] = 0.f;

    for (int kt = 0; kt < 64; kt++) {
        int k0 = kt * 16;
        float4 a4 = *(const float4*)(A  + (size_t)(m0 + lm) * HW + k0 + lk);
        float4 b4 = *(const float4*)(Bm + (size_t)(n0 + lm) * HW + k0 + lk);
        As[lk + 0][lm] = a4.x; As[lk + 1][lm] = a4.y; As[lk + 2][lm] = a4.z; As[lk + 3][lm] = a4.w;
        Bs[lk + 0][lm] = b4.x; Bs[lk + 1][lm] = b4.y; Bs[lk + 2][lm] = b4.z; Bs[lk + 3][lm] = b4.w;
        __syncthreads();
#pragma unroll
        for (int k2 = 0; k2 < 16; k2++) {
            float4 av = *(const float4*)&As[k2][ty * 4];
            float4 bv = *(const float4*)&Bs[k2][tx * 4];
            fma44(acc, av, bv);
        }
        __syncthreads();
    }
    float* outp = attout + (size_t)b * CC * HW + (size_t)m0 * HW + n0;
#pragma unroll
    for (int i = 0; i < 4; i++) {
        float4 o = make_float4(acc[i][0], acc[i][1], acc[i][2], acc[i][3]);
        *(float4*)(outp + (size_t)(ty * 4 + i) * HW + tx * 4) = o;
    }
}

// ---------------- inverse channel norms of f_q and att_fq ----------------
__global__ void k_norm2(const float* __restrict__ f_q, const float* __restrict__ att) {
    int b   = blockIdx.y;
    int pix = blockIdx.x * 256 + threadIdx.x;
    const float* src = (blockIdx.z == 0 ? f_q : att) + (size_t)b * CC * HW + pix;
    float ss = 0.f;
#pragma unroll 8
    for (int c = 0; c < CC; c++) { float v = src[(size_t)c * HW]; ss = fmaf(v, v, ss); }
    float inv = 1.0f / fmaxf(sqrtf(ss), 1e-12f);
    (blockIdx.z == 0 ? g_nq2 : g_na2)[b * HW + pix] = inv;
}

// ---------------- fq = l2n(f_q) + 0.5*l2n(att_fq) ----------------
__global__ void k_fqout(const float* __restrict__ f_q, const float* __restrict__ att,
                        float* __restrict__ fqo) {
    int i4 = blockIdx.x * 256 + threadIdx.x;          // < 524288
    int base = i4 * 4;
    int b = base >> 19;
    int pix = base & 1023;
    float4 q = ((const float4*)f_q)[i4];
    float4 a = ((const float4*)att)[i4];
    int ni = (b * HW + pix) >> 2;
    float4 nq = ((const float4*)g_nq2)[ni];
    float4 na = ((const float4*)g_na2)[ni];
    float4 o;
    o.x = q.x * nq.x + a.x * na.x * 0.5f;
    o.y = q.y * nq.y + a.y * na.y * 0.5f;
    o.z = q.z * nq.z + a.z * na.z * 0.5f;
    o.w = q.w * nq.w + a.w * na.w * 0.5f;
    ((float4*)fqo)[i4] = o;
}

// ---------------- conv1: bf16-split tensor implicit GEMM ----------------
// Output tile 64(oc) x 128(pix); K = 9 taps x 1024 ic, k-tile 16, double-buffered.
// W smem rows 72 halves (144 B), I smem rows 136 halves (272 B): conflict-free ldsm.trans.
__global__ void __launch_bounds__(256, 2) k_conv1(const float* __restrict__ f_q,
                                                  const float* __restrict__ f_s,
                                                  const float* __restrict__ b1) {
    __shared__ __align__(16) unsigned smW[2][2][16][36];  // [buf][hi/lo][k][oc72h]
    __shared__ __align__(16) unsigned smI[2][2][16][68];  // [buf][hi/lo][k][pix136h]
    int b = blockIdx.z, oc0 = blockIdx.y * 64, pix0 = blockIdx.x * 128;
    int tid = threadIdx.x, lane = tid & 31, wid = tid >> 5;
    int wm = (wid >> 2) * 32, wn = (wid & 3) * 32;
    int kr = tid >> 4, mc = (tid & 15) * 8;

    int kA = (lane & 7) + ((lane >> 4) << 3);
    int cA = ((lane >> 3) & 1) << 3;
    int kB = (lane & 7) + (((lane >> 3) & 1) << 3);
    int cB = (lane >> 4) << 3;
    unsigned baseW = (unsigned)__cvta_generic_to_shared(&smW[0][0][0][0]);
    unsigned baseI = (unsigned)__cvta_generic_to_shared(&smI[0][0][0][0]);
    unsigned offA = (unsigned)(kA * 144 + (cA + wm) * 2);
    unsigned offB = (unsigned)(kB * 272 + (cB + wn) * 2);

    const float* fqp = f_q + (size_t)b * CC * HW;
    const float* fsp = f_s + (size_t)b * CC * HW;

    // loader pixel coords: 8 consecutive pixels share one image row (8 | 32)
    int pp0 = pix0 + mc;
    int py = pp0 >> 5, px0v = pp0 & 31;
    // weight loader coords
    int wtt = (tid & 127);
    int wrow = wtt >> 3, wcol8 = (wtt & 7) * 8;
    bool whalf = (tid < 128);

    float c[2][4][4];
#pragma unroll
    for (int f = 0; f < 2; f++)
#pragma unroll
        for (int g = 0; g < 4; g++) { c[f][g][0]=0.f; c[f][g][1]=0.f; c[f][g][2]=0.f; c[f][g][3]=0.f; }

    // ---- prologue: kt = 0 (tap 0, ict 0, dy=-2, dx=-2) ----
    {
        uint4 wv;
        const __nv_bfloat16* wsrc = whalf ? g_wt1h : g_wt1l;
        wv = *(const uint4*)(wsrc + (size_t)(0 * 1024 + wrow) * 256 + oc0 + wcol8);
        float v[8];
        int ic = kr;
        const float* src = fqp + (size_t)ic * HW;
        int iy = py - 2;
        bool yok = ((unsigned)iy < 32u);
        const float* rowp = src + iy * 32;
#pragma unroll
        for (int j = 0; j < 8; j++) {
            int ix = px0v + j - 2;
            v[j] = (yok && ((unsigned)ix < 32u)) ? rowp[ix] : 0.f;
        }
        *(uint4*)&smW[0][whalf ? 0 : 1][wrow][wcol8 >> 1] = wv;
        unsigned h0,h1,l0,l1;
        unsigned* pIh = &smI[0][0][kr][mc >> 1];
        unsigned* pIl = &smI[0][1][kr][mc >> 1];
        float4 fa = make_float4(v[0], v[1], v[2], v[3]);
        float4 fb = make_float4(v[4], v[5], v[6], v[7]);
        cvt_hl(fa,h0,h1,l0,l1); pIh[0]=h0; pIh[1]=h1; pIl[0]=l0; pIl[1]=l1;
        cvt_hl(fb,h0,h1,l0,l1); pIh[2]=h0; pIh[3]=h1; pIl[2]=l0; pIl[3]=l1;
    }
    __syncthreads();

    int buf = 0;
    for (int kt = 0; kt < 576; kt++) {
        uint4 wv; float v[8];
        if (kt < 575) {
            int kn = kt + 1;
            int tap = kn >> 6, ict = kn & 63;
            int dy = 2 * (tap / 3) - 2, dx = 2 * (tap % 3) - 2;
            const __nv_bfloat16* wsrc = whalf ? g_wt1h : g_wt1l;
            wv = *(const uint4*)(wsrc + (size_t)(tap * 1024 + ict * 16 + wrow) * 256 + oc0 + wcol8);
            int ic = ict * 16 + kr;
            const float* src = (ic < 512 ? fqp + (size_t)ic * HW
                                         : fsp + (size_t)(ic - 512) * HW);
            int iy = py + dy;
            bool yok = ((unsigned)iy < 32u);
            const float* rowp = src + iy * 32;
#pragma unroll
            for (int j = 0; j < 8; j++) {
                int ix = px0v + j + dx;
                v[j] = (yok && ((unsigned)ix < 32u)) ? rowp[ix] : 0.f;
            }
        }
        unsigned bW = baseW + (unsigned)buf * 4608u;
        unsigned bI = baseI + (unsigned)buf * 8704u;
        unsigned a[8], al[8], bh[8], bl[8];
#pragma unroll
        for (int f = 0; f < 2; f++) ldsm4t(a  + 4 * f, bW + offA + f * 32);
#pragma unroll
        for (int f = 0; f < 2; f++) ldsm4t(al + 4 * f, bW + 2304u + offA + f * 32);
#pragma unroll
        for (int g2 = 0; g2 < 2; g2++) ldsm4t(bh + 4 * g2, bI + offB + g2 * 32);
#pragma unroll
        for (int g2 = 0; g2 < 2; g2++) ldsm4t(bl + 4 * g2, bI + 4352u + offB + g2 * 32);
#pragma unroll
        for (int f = 0; f < 2; f++)
#pragma unroll
            for (int g = 0; g < 4; g++) {
                mma_bf16(c[f][g], a  + 4 * f, bh + 2 * g);
                mma_bf16(c[f][g], a  + 4 * f, bl + 2 * g);
                mma_bf16(c[f][g], al + 4 * f, bh + 2 * g);
            }
        if (kt < 575) {
            int nb = buf ^ 1;
            *(uint4*)&smW[nb][whalf ? 0 : 1][wrow][wcol8 >> 1] = wv;
            unsigned h0,h1,l0,l1;
            unsigned* pIh = &smI[nb][0][kr][mc >> 1];
            unsigned* pIl = &smI[nb][1][kr][mc >> 1];
            float4 fa = make_float4(v[0], v[1], v[2], v[3]);
            float4 fb = make_float4(v[4], v[5], v[6], v[7]);
            cvt_hl(fa,h0,h1,l0,l1); pIh[0]=h0; pIh[1]=h1; pIl[0]=l0; pIl[1]=l1;
            cvt_hl(fb,h0,h1,l0,l1); pIh[2]=h0; pIh[3]=h1; pIl[2]=l0; pIl[3]=l1;
            __syncthreads();
            buf = nb;
        }
    }

    float* outp = g_c1 + (size_t)b * 262144;
#pragma unroll
    for (int f = 0; f < 2; f++) {
        int r0 = wm + f * 16 + (lane >> 2), r1 = r0 + 8;
        float bias0 = b1[oc0 + r0], bias1 = b1[oc0 + r1];
#pragma unroll
        for (int g = 0; g < 4; g++) {
            int cb = wn + g * 8 + (lane & 3) * 2;
            float2 o0 = make_float2(fmaxf(c[f][g][0] + bias0, 0.f),
                                    fmaxf(c[f][g][1] + bias0, 0.f));
            float2 o1 = make_float2(fmaxf(c[f][g][2] + bias1, 0.f),
                                    fmaxf(c[f][g][3] + bias1, 0.f));
            *(float2*)(outp + (size_t)(oc0 + r0) * HW + pix0 + cb) = o0;
            *(float2*)(outp + (size_t)(oc0 + r1) * HW + pix0 + cb) = o1;
        }
    }
}

// ---------------- conv2: implicit GEMM, 3x3 VALID on 32x32 -> 30x30, +bias ----------------
__global__ void k_conv2(const float* __restrict__ b2) {
    __shared__ __align__(16) float Ws[16][64];
    __shared__ __align__(16) float Is[16][64];
    int b = blockIdx.z, oc0 = blockIdx.y * 64, n0 = blockIdx.x * 64;
    int tid = threadIdx.x, tx = tid & 15, ty = tid >> 4;
    int kk = (tid * 4) >> 6, nn0 = (tid * 4) & 63;

    int py[4], px[4];
#pragma unroll
    for (int j = 0; j < 4; j++) {
        int p = n0 + nn0 + j; if (p > 899) p = 899;
        py[j] = p / 30; px[j] = p % 30;
    }

    float acc[4][4];
#pragma unroll
    for (int i = 0; i < 4; i++)
#pragma unroll
        for (int j = 0; j < 4; j++) acc[i][j] = 0.f;

    for (int tap = 0; tap < 9; tap++) {
        int dy = tap / 3, dx = tap % 3;
        int off[4];
#pragma unroll
        for (int j = 0; j < 4; j++) off[j] = (py[j] + dy) * 32 + (px[j] + dx);
        const float* wb = g_wt2 + tap * 65536 + oc0;
        for (int ict = 0; ict < 16; ict++) {
            int ic0 = ict * 16;
            float4 wv = *(const float4*)(wb + (ic0 + kk) * 256 + nn0);
            *(float4*)&Ws[kk][nn0] = wv;
            const float* ib = g_c1 + (size_t)b * 262144 + (size_t)(ic0 + kk) * HW;
#pragma unroll
            for (int j = 0; j < 4; j++) Is[kk][nn0 + j] = ib[off[j]];
            __syncthreads();
#pragma unroll
            for (int k2 = 0; k2 < 16; k2++) {
                float4 w4 = *(const float4*)&Ws[k2][ty * 4];
                float4 i4 = *(const float4*)&Is[k2][tx * 4];
                fma44(acc, w4, i4);
            }
            __syncthreads();
        }
    }
#pragma unroll
    for (int i = 0; i < 4; i++) {
        int oc = oc0 + ty * 4 + i;
        float bias = b2[oc];
#pragma unroll
        for (int j = 0; j < 4; j++) {
            int p = n0 + tx * 4 + j;
            if (p < 900) g_c2[(size_t)b * 230400 + (size_t)oc * 900 + p] = acc[i][j] + bias;
        }
    }
}

// ---------------- 3x3 stride-3 maxpool: 30x30 -> 10x10 ----------------
__global__ void k_pool() {
    int oc = blockIdx.x, b = blockIdx.y;
    int t = threadIdx.x;
    if (t >= 100) return;
    int y = t / 10, x = t % 10;
    const float* in = g_c2 + ((size_t)b * 256 + oc) * 900;
    float m = -3.4e38f;
#pragma unroll
    for (int dy = 0; dy < 3; dy++)
#pragma unroll
        for (int dx = 0; dx < 3; dx++)
            m = fmaxf(m, in[(3 * y + dy) * 30 + 3 * x + dx]);
    g_pool[((size_t)b * 256 + oc) * 100 + t] = m;
}

// ---------------- conv3 (3x3 VALID, 10x10 -> 8x8) + mean -> weight[b] ----------------
__global__ void k_conv3(const float* __restrict__ w3, const float* __restrict__ b3,
                        float* __restrict__ wout) {
    int b = blockIdx.x;
    int tid = threadIdx.x;
    int o = tid >> 2, part = tid & 3;         // 64 outputs x 4 partial sums
    int oy = o >> 3, ox = o & 7;
    float s = 0.f;
    for (int ic = part * 64; ic < part * 64 + 64; ic++) {
        const float* pp = g_pool + ((size_t)b * 256 + ic) * 100 + oy * 10 + ox;
        const float* wp = w3 + ic * 9;
#pragma unroll
        for (int ky = 0; ky < 3; ky++)
#pragma unroll
            for (int kx = 0; kx < 3; kx++)
                s = fmaf(pp[ky * 10 + kx], wp[ky * 3 + kx], s);
    }
    s += __shfl_down_sync(0xffffffffu, s, 1);
    s += __shfl_down_sync(0xffffffffu, s, 2);
    __shared__ float sh[64];
    if (part == 0) sh[o] = s;
    __syncthreads();
    if (tid < 32) {
        float v = sh[tid] + sh[tid + 32];
#pragma unroll
        for (int off = 16; off; off >>= 1) v += __shfl_xor_sync(0xffffffffu, v, off);
        if (tid == 0) wout[b] = v * (1.0f / 64.0f) + b3[0];
    }
}

// ---------------- launch ----------------
extern "C" void kernel_launch(void* const* d_in, const int* in_sizes, int n_in,
                              void* d_out, int out_size) {
    const float* fq_feats = (const float*)d_in[0];
    const float* fs_feats = (const float*)d_in[1];
    const float* f_q = (const float*)d_in[2];
    const float* f_s = (const float*)d_in[3];
    const float* w1 = (const float*)d_in[4];
    const float* b1 = (const float*)d_in[5];
    const float* w2 = (const float*)d_in[6];
    const float* b2 = (const float*)d_in[7];
    const float* w3 = (const float*)d_in[8];
    const float* b3 = (const float*)d_in[9];

    float* out     = (float*)d_out;
    float* fq_out  = out;                       // [4,512,32,32]
    float* att_out = out + 2097152;             // [4,512,32,32]
    float* w_out   = out + 4194304;             // [1,4]

    k_twt1<<<9216, 256>>>(w1);
    k_twt2<<<2304, 256>>>(w2);
    k_norms<<<dim3(4, 36, 2), 256>>>(fq_feats, fs_feats);
    k_corr<<<dim3(8, 8, 4), 256>>>(fq_feats, fs_feats);
    k_softmax<<<4096, 256>>>();
    k_att<<<dim3(16, 8, 4), 256>>>(f_s, att_out);
    k_norm2<<<dim3(4, 4, 2), 256>>>(f_q, att_out);
    k_fqout<<<2048, 256>>>(f_q, att_out, fq_out);
    k_conv1<<<dim3(8, 4, 4), 256>>>(f_q, f_s, b1);
    k_conv2<<<dim3(15, 4, 4), 256>>>(b2);
    k_pool<<<dim3(256, 4), 128>>>();
    k_conv3<<<4, 256>>>(w3, b3, w_out);
}

// round 8
// speedup vs baseline: 2.4542x; 1.1169x over previous
#include <cuda_runtime.h>
#include <cuda_bf16.h>

#define LL 9
#define BB 4
#define CC 512
#define HW 1024

// ---------------- scratch (device globals; no allocation) ----------------
__device__ __align__(16) float g_invq[LL*BB*HW];
__device__ __align__(16) float g_invs[LL*BB*HW];
__device__ __align__(16) float g_corr[(size_t)BB*HW*HW];   // 16 MB, reused as attn
__device__ __align__(16) float g_c1[BB*256*HW];            // conv1 out [b][256][32*32]
__device__ __align__(16) float g_c2[BB*256*900];           // conv2 out [b][256][30*30]
__device__ __align__(16) float g_pool[BB*256*100];         // pooled [b][256][10*10]
__device__ __align__(16) __nv_bfloat16 g_wt1h[9*1024*256]; // w1 hi [tap][ic][oc]
__device__ __align__(16) __nv_bfloat16 g_wt1l[9*1024*256]; // w1 lo [tap][ic][oc]
__device__ __align__(16) __nv_bfloat16 g_wt2h[9*256*256];  // w2 hi [tap][ic][oc]
__device__ __align__(16) __nv_bfloat16 g_wt2l[9*256*256];  // w2 lo [tap][ic][oc]
__device__ __align__(16) float g_nq2[BB*HW];
__device__ __align__(16) float g_na2[BB*HW];

// ---------------- helpers ----------------
__device__ __forceinline__ void ldsm4t(unsigned* r, unsigned addr) {
    asm volatile("ldmatrix.sync.aligned.m8n8.x4.trans.shared.b16 {%0,%1,%2,%3}, [%4];\n"
        : "=r"(r[0]), "=r"(r[1]), "=r"(r[2]), "=r"(r[3]) : "r"(addr));
}
__device__ __forceinline__ void ldsm4(unsigned* r, unsigned addr) {
    asm volatile("ldmatrix.sync.aligned.m8n8.x4.shared.b16 {%0,%1,%2,%3}, [%4];\n"
        : "=r"(r[0]), "=r"(r[1]), "=r"(r[2]), "=r"(r[3]) : "r"(addr));
}
__device__ __forceinline__ void mma_bf16(float* c, const unsigned* a, const unsigned* b) {
    asm volatile(
        "mma.sync.aligned.m16n8k16.row.col.f32.bf16.bf16.f32 "
        "{%0,%1,%2,%3}, {%4,%5,%6,%7}, {%8,%9}, {%0,%1,%2,%3};\n"
        : "+f"(c[0]), "+f"(c[1]), "+f"(c[2]), "+f"(c[3])
        : "r"(a[0]), "r"(a[1]), "r"(a[2]), "r"(a[3]), "r"(b[0]), "r"(b[1]));
}
// split float4 -> hi bf16x2 pair + lo bf16x2 pair (packed as unsigned)
__device__ __forceinline__ void cvt_hl(float4 v, unsigned& h0, unsigned& h1,
                                       unsigned& l0, unsigned& l1) {
    __nv_bfloat162 H0 = __floats2bfloat162_rn(v.x, v.y);
    __nv_bfloat162 H1 = __floats2bfloat162_rn(v.z, v.w);
    __nv_bfloat162 L0 = __floats2bfloat162_rn(v.x - __bfloat162float(H0.x),
                                              v.y - __bfloat162float(H0.y));
    __nv_bfloat162 L1 = __floats2bfloat162_rn(v.z - __bfloat162float(H1.x),
                                              v.w - __bfloat162float(H1.y));
    h0 = *(unsigned*)&H0; h1 = *(unsigned*)&H1;
    l0 = *(unsigned*)&L0; l1 = *(unsigned*)&L1;
}

// ---------------- weight prep ----------------
__global__ void k_twt1(const float* __restrict__ w1) {
    int i = blockIdx.x * 256 + threadIdx.x;          // < 2359296
    float v = w1[i];
    int oc = i / 9216; int r = i % 9216; int ic = r / 9; int tap = r % 9;
    __nv_bfloat16 h = __float2bfloat16(v);
    __nv_bfloat16 lo = __float2bfloat16(v - __bfloat162float(h));
    int o = tap * 262144 + ic * 256 + oc;
    g_wt1h[o] = h; g_wt1l[o] = lo;
}
__global__ void k_twt2(const float* __restrict__ w2) {
    int i = blockIdx.x * 256 + threadIdx.x;          // < 589824
    float v = w2[i];
    int oc = i / 2304; int r = i % 2304; int ic = r / 9; int tap = r % 9;
    __nv_bfloat16 h = __float2bfloat16(v);
    __nv_bfloat16 lo = __float2bfloat16(v - __bfloat162float(h));
    int o = tap * 65536 + ic * 256 + oc;
    g_wt2h[o] = h; g_wt2l[o] = lo;
}

// ---------------- per-level per-pixel inverse channel norms ----------------
__global__ void k_norms(const float* __restrict__ fq, const float* __restrict__ fs) {
    int lb  = blockIdx.y;                             // 0..35 (l*B+b)
    int pix = blockIdx.x * 256 + threadIdx.x;         // 0..1023
    const float* src = (blockIdx.z == 0 ? fq : fs) + (size_t)lb * CC * HW + pix;
    float ss = 0.f;
#pragma unroll 8
    for (int c = 0; c < CC; c++) { float v = src[(size_t)c * HW]; ss = fmaf(v, v, ss); }
    float inv = 1.0f / fmaxf(sqrtf(ss), 1e-12f);
    (blockIdx.z == 0 ? g_invq : g_invs)[lb * HW + pix] = inv;
}

// ---------------- corr: bf16-split tensor-core (proven) ----------------
__global__ void __launch_bounds__(256, 2) k_corr(const float* __restrict__ fq,
                                                 const float* __restrict__ fs) {
    __shared__ __align__(16) unsigned smq[2][4][16][68];  // 68 u32 = 136 halves
    int b  = blockIdx.z;
    int m0 = blockIdx.y * 128, n0 = blockIdx.x * 128;
    int tid = threadIdx.x, lane = tid & 31, wid = tid >> 5;
    int wm = (wid >> 2) * 64, wn = (wid & 3) * 32;
    int kr = tid >> 4, mc = (tid & 15) * 8;           // loader: 16 k-rows x 8 floats

    int kA = (lane & 7) + ((lane >> 4) << 3);
    int cA = ((lane >> 3) & 1) << 3;
    int kB = (lane & 7) + (((lane >> 3) & 1) << 3);
    int cB = (lane >> 4) << 3;
    unsigned smbase = (unsigned)__cvta_generic_to_shared(&smq[0][0][0][0]);
    unsigned offA = (unsigned)(kA * 272 + (cA + wm) * 2);
    unsigned offB = (unsigned)(kB * 272 + (cB + wn) * 2);

    float* outp = g_corr + (size_t)b * HW * HW + (size_t)m0 * HW + n0;

    for (int l = 0; l < LL; l++) {
        const float* Ag = fq + (size_t)(l * BB + b) * CC * HW + m0;
        const float* Bg = fs + (size_t)(l * BB + b) * CC * HW + n0;

        float c[4][4][4];
#pragma unroll
        for (int f = 0; f < 4; f++)
#pragma unroll
            for (int g = 0; g < 4; g++) { c[f][g][0]=0.f; c[f][g][1]=0.f; c[f][g][2]=0.f; c[f][g][3]=0.f; }

        __syncthreads();                              // smem reuse across levels
        {   // prologue: k-tile 0 -> buf 0
            float4 a0g = *(const float4*)(Ag + (size_t)kr * HW + mc);
            float4 a1g = *(const float4*)(Ag + (size_t)kr * HW + mc + 4);
            float4 b0g = *(const float4*)(Bg + (size_t)kr * HW + mc);
            float4 b1g = *(const float4*)(Bg + (size_t)kr * HW + mc + 4);
            unsigned h0,h1,l0,l1;
            unsigned* pAh = &smq[0][0][kr][mc >> 1];
            unsigned* pAl = &smq[0][1][kr][mc >> 1];
            unsigned* pBh = &smq[0][2][kr][mc >> 1];
            unsigned* pBl = &smq[0][3][kr][mc >> 1];
            cvt_hl(a0g,h0,h1,l0,l1); pAh[0]=h0; pAh[1]=h1; pAl[0]=l0; pAl[1]=l1;
            cvt_hl(a1g,h0,h1,l0,l1); pAh[2]=h0; pAh[3]=h1; pAl[2]=l0; pAl[3]=l1;
            cvt_hl(b0g,h0,h1,l0,l1); pBh[0]=h0; pBh[1]=h1; pBl[0]=l0; pBl[1]=l1;
            cvt_hl(b1g,h0,h1,l0,l1); pBh[2]=h0; pBh[3]=h1; pBl[2]=l0; pBl[3]=l1;
        }
        __syncthreads();

        int buf = 0;
        for (int kt = 0; kt < 32; kt++) {
            float4 a0g, a1g, b0g, b1g;
            if (kt < 31) {
                int k0 = (kt + 1) * 16;
                a0g = *(const float4*)(Ag + (size_t)(k0 + kr) * HW + mc);
                a1g = *(const float4*)(Ag + (size_t)(k0 + kr) * HW + mc + 4);
                b0g = *(const float4*)(Bg + (size_t)(k0 + kr) * HW + mc);
                b1g = *(const float4*)(Bg + (size_t)(k0 + kr) * HW + mc + 4);
            }
            unsigned base = smbase + (unsigned)buf * 17408u;
            unsigned a[16], bh[8], bl[8];
#pragma unroll
            for (int f = 0; f < 4; f++) ldsm4t(a + 4 * f, base + offA + f * 32);
#pragma unroll
            for (int g2 = 0; g2 < 2; g2++) ldsm4t(bh + 4 * g2, base + 2u * 4352u + offB + g2 * 32);
#pragma unroll
            for (int g2 = 0; g2 < 2; g2++) ldsm4t(bl + 4 * g2, base + 3u * 4352u + offB + g2 * 32);
#pragma unroll
            for (int f = 0; f < 4; f++)
#pragma unroll
                for (int g = 0; g < 4; g++) {
                    mma_bf16(c[f][g], a + 4 * f, bh + 2 * g);
                    mma_bf16(c[f][g], a + 4 * f, bl + 2 * g);
                }
#pragma unroll
            for (int f = 0; f < 4; f++) ldsm4t(a + 4 * f, base + 4352u + offA + f * 32);
#pragma unroll
            for (int f = 0; f < 4; f++)
#pragma unroll
                for (int g = 0; g < 4; g++)
                    mma_bf16(c[f][g], a + 4 * f, bh + 2 * g);

            if (kt < 31) {
                int nb = buf ^ 1;
                unsigned h0,h1,l0,l1;
                unsigned* pAh = &smq[nb][0][kr][mc >> 1];
                unsigned* pAl = &smq[nb][1][kr][mc >> 1];
                unsigned* pBh = &smq[nb][2][kr][mc >> 1];
                unsigned* pBl = &smq[nb][3][kr][mc >> 1];
                cvt_hl(a0g,h0,h1,l0,l1); pAh[0]=h0; pAh[1]=h1; pAl[0]=l0; pAl[1]=l1;
                cvt_hl(a1g,h0,h1,l0,l1); pAh[2]=h0; pAh[3]=h1; pAl[2]=l0; pAl[3]=l1;
                cvt_hl(b0g,h0,h1,l0,l1); pBh[0]=h0; pBh[1]=h1; pBl[0]=l0; pBl[1]=l1;
                cvt_hl(b1g,h0,h1,l0,l1); pBh[2]=h0; pBh[3]=h1; pBl[2]=l0; pBl[3]=l1;
                __syncthreads();
                buf = nb;
            }
        }

        const float* iq = g_invq + (l * BB + b) * HW + m0;
        const float* is = g_invs + (l * BB + b) * HW + n0;
#pragma unroll
        for (int f = 0; f < 4; f++) {
            int r0 = wm + f * 16 + (lane >> 2), r1 = r0 + 8;
            float q0 = iq[r0], q1 = iq[r1];
#pragma unroll
            for (int g = 0; g < 4; g++) {
                int cb = wn + g * 8 + (lane & 3) * 2;
                float s0 = is[cb], s1 = is[cb + 1];
                float v00 = fmaxf(c[f][g][0] * q0 * s0, 0.f);
                float v01 = fmaxf(c[f][g][1] * q0 * s1, 0.f);
                float v10 = fmaxf(c[f][g][2] * q1 * s0, 0.f);
                float v11 = fmaxf(c[f][g][3] * q1 * s1, 0.f);
                float2* p0 = (float2*)(outp + (size_t)r0 * HW + cb);
                float2* p1 = (float2*)(outp + (size_t)r1 * HW + cb);
                if (l == 0) {
                    *p0 = make_float2(v00, v01);
                    *p1 = make_float2(v10, v11);
                } else {
                    float2 o0 = *p0, o1 = *p1;
                    o0.x += v00; o0.y += v01; o1.x += v10; o1.y += v11;
                    *p0 = o0; *p1 = o1;
                }
            }
        }
    }
}

// ---------------- row softmax (scale = TEMP/L folds the mean) ----------------
__global__ void k_softmax() {
    float* r = g_corr + (size_t)blockIdx.x * HW;      // blockIdx.x = b*1024 + q
    int tid = threadIdx.x, wid = tid >> 5, lane = tid & 31;
    const float sc = 20.0f / 9.0f;
    float4 v = ((const float4*)r)[tid];
    v.x *= sc; v.y *= sc; v.z *= sc; v.w *= sc;
    float mx = fmaxf(fmaxf(v.x, v.y), fmaxf(v.z, v.w));
#pragma unroll
    for (int o = 16; o; o >>= 1) mx = fmaxf(mx, __shfl_xor_sync(0xffffffffu, mx, o));
    __shared__ float sh[8];
    if (lane == 0) sh[wid] = mx;
    __syncthreads();
    float m = sh[0];
#pragma unroll
    for (int k = 1; k < 8; k++) m = fmaxf(m, sh[k]);
    v.x = __expf(v.x - m); v.y = __expf(v.y - m);
    v.z = __expf(v.z - m); v.w = __expf(v.w - m);
    float s = v.x + v.y + v.z + v.w;
#pragma unroll
    for (int o = 16; o; o >>= 1) s += __shfl_xor_sync(0xffffffffu, s, o);
    __syncthreads();
    if (lane == 0) sh[wid] = s;
    __syncthreads();
    float tot = 0.f;
#pragma unroll
    for (int k = 0; k < 8; k++) tot += sh[k];
    float inv = 1.0f / tot;
    v.x *= inv; v.y *= inv; v.z *= inv; v.w *= inv;
    ((float4*)r)[tid] = v;
}

// ---------------- k_att: bf16-split MMA, non-trans ldmatrix (both operands k-contig) ----
__global__ void __launch_bounds__(256, 2) k_att(const float* __restrict__ fs_in,
                                                float* __restrict__ attout) {
    __shared__ __align__(16) uint4 smA[2][2][2][128];   // [buf][hl][kb][row]
    __shared__ __align__(16) uint4 smB[2][2][2][128];
    int b = blockIdx.z;
    int m0 = blockIdx.y * 128, n0 = blockIdx.x * 128;
    int tid = threadIdx.x, lane = tid & 31, wid = tid >> 5;
    int wm = (wid >> 2) * 64, wn = (wid & 3) * 32;
    int lrow = tid >> 1, lkb = tid & 1;

    const float* Ag = fs_in + (size_t)b * CC * HW + (size_t)m0 * HW;
    const float* Bg = g_corr + (size_t)b * HW * HW + (size_t)n0 * HW;

    int rsel = ((lane >> 3) & 1) * 8 + (lane & 7);
    int kbsel = lane >> 4;
    unsigned baseA = (unsigned)__cvta_generic_to_shared(&smA[0][0][0][0]);
    unsigned baseB = (unsigned)__cvta_generic_to_shared(&smB[0][0][0][0]);
    unsigned offA = (unsigned)(kbsel * 2048 + (wm + rsel) * 16);     // + f*256
    unsigned offB = (unsigned)(kbsel * 2048 + (wn + rsel) * 16);     // + gg*256

    float c[4][4][4];
#pragma unroll
    for (int f = 0; f < 4; f++)
#pragma unroll
        for (int g = 0; g < 4; g++) { c[f][g][0]=0.f; c[f][g][1]=0.f; c[f][g][2]=0.f; c[f][g][3]=0.f; }

    {   // prologue: k-tile 0
        float4 a0g = *(const float4*)(Ag + (size_t)lrow * HW + lkb * 8);
        float4 a1g = *(const float4*)(Ag + (size_t)lrow * HW + lkb * 8 + 4);
        float4 b0g = *(const float4*)(Bg + (size_t)lrow * HW + lkb * 8);
        float4 b1g = *(const float4*)(Bg + (size_t)lrow * HW + lkb * 8 + 4);
        unsigned h0,h1,l0,l1,h2,h3,l2,l3;
        cvt_hl(a0g,h0,h1,l0,l1); cvt_hl(a1g,h2,h3,l2,l3);
        smA[0][0][lkb][lrow] = make_uint4(h0,h1,h2,h3);
        smA[0][1][lkb][lrow] = make_uint4(l0,l1,l2,l3);
        cvt_hl(b0g,h0,h1,l0,l1); cvt_hl(b1g,h2,h3,l2,l3);
        smB[0][0][lkb][lrow] = make_uint4(h0,h1,h2,h3);
        smB[0][1][lkb][lrow] = make_uint4(l0,l1,l2,l3);
    }
    __syncthreads();

    int buf = 0;
    for (int kt = 0; kt < 64; kt++) {
        float4 a0g, a1g, b0g, b1g;
        if (kt < 63) {
            int k0 = (kt + 1) * 16 + lkb * 8;
            a0g = *(const float4*)(Ag + (size_t)lrow * HW + k0);
            a1g = *(const float4*)(Ag + (size_t)lrow * HW + k0 + 4);
            b0g = *(const float4*)(Bg + (size_t)lrow * HW + k0);
            b1g = *(const float4*)(Bg + (size_t)lrow * HW + k0 + 4);
        }
        unsigned bA = baseA + (unsigned)buf * 8192u;
        unsigned bB = baseB + (unsigned)buf * 8192u;
        unsigned a[16], bh[8], bl[8], t[4];
#pragma unroll
        for (int f = 0; f < 4; f++) ldsm4(a + 4 * f, bA + offA + f * 256);
#pragma unroll
        for (int gg = 0; gg < 2; gg++) {
            ldsm4(t, bB + offB + gg * 256);
            bh[gg*4+0]=t[0]; bh[gg*4+1]=t[2]; bh[gg*4+2]=t[1]; bh[gg*4+3]=t[3];
        }
#pragma unroll
        for (int gg = 0; gg < 2; gg++) {
            ldsm4(t, bB + 4096u + offB + gg * 256);
            bl[gg*4+0]=t[0]; bl[gg*4+1]=t[2]; bl[gg*4+2]=t[1]; bl[gg*4+3]=t[3];
        }
#pragma unroll
        for (int f = 0; f < 4; f++)
#pragma unroll
            for (int g = 0; g < 4; g++) {
                mma_bf16(c[f][g], a + 4 * f, bh + 2 * g);
                mma_bf16(c[f][g], a + 4 * f, bl + 2 * g);
            }
#pragma unroll
        for (int f = 0; f < 4; f++) ldsm4(a + 4 * f, bA + 4096u + offA + f * 256);
#pragma unroll
        for (int f = 0; f < 4; f++)
#pragma unroll
            for (int g = 0; g < 4; g++)
                mma_bf16(c[f][g], a + 4 * f, bh + 2 * g);

        if (kt < 63) {
            int nb = buf ^ 1;
            unsigned h0,h1,l0,l1,h2,h3,l2,l3;
            cvt_hl(a0g,h0,h1,l0,l1); cvt_hl(a1g,h2,h3,l2,l3);
            smA[nb][0][lkb][lrow] = make_uint4(h0,h1,h2,h3);
            smA[nb][1][lkb][lrow] = make_uint4(l0,l1,l2,l3);
            cvt_hl(b0g,h0,h1,l0,l1); cvt_hl(b1g,h2,h3,l2,l3);
            smB[nb][0][lkb][lrow] = make_uint4(h0,h1,h2,h3);
            smB[nb][1][lkb][lrow] = make_uint4(l0,l1,l2,l3);
            __syncthreads();
            buf = nb;
        }
    }

    float* outp = attout + (size_t)b * CC * HW + (size_t)m0 * HW + n0;
#pragma unroll
    for (int f = 0; f < 4; f++) {
        int r0 = wm + f * 16 + (lane >> 2), r1 = r0 + 8;
#pragma unroll
        for (int g = 0; g < 4; g++) {
            int cb = wn + g * 8 + (lane & 3) * 2;
            *(float2*)(outp + (size_t)r0 * HW + cb) = make_float2(c[f][g][0], c[f][g][1]);
            *(float2*)(outp + (size_t)r1 * HW + cb) = make_float2(c[f][g][2], c[f][g][3]);
        }
    }
}

// ---------------- inverse channel norms of f_q and att_fq ----------------
__global__ void k_norm2(const float* __restrict__ f_q, const float* __restrict__ att) {
    int b   = blockIdx.y;
    int pix = blockIdx.x * 256 + threadIdx.x;
    const float* src = (blockIdx.z == 0 ? f_q : att) + (size_t)b * CC * HW + pix;
    float ss = 0.f;
#pragma unroll 8
    for (int c = 0; c < CC; c++) { float v = src[(size_t)c * HW]; ss = fmaf(v, v, ss); }
    float inv = 1.0f / fmaxf(sqrtf(ss), 1e-12f);
    (blockIdx.z == 0 ? g_nq2 : g_na2)[b * HW + pix] = inv;
}

// ---------------- fq = l2n(f_q) + 0.5*l2n(att_fq) ----------------
__global__ void k_fqout(const float* __restrict__ f_q, const float* __restrict__ att,
                        float* __restrict__ fqo) {
    int i4 = blockIdx.x * 256 + threadIdx.x;          // < 524288
    int base = i4 * 4;
    int b = base >> 19;
    int pix = base & 1023;
    float4 q = ((const float4*)f_q)[i4];
    float4 a = ((const float4*)att)[i4];
    int ni = (b * HW + pix) >> 2;
    float4 nq = ((const float4*)g_nq2)[ni];
    float4 na = ((const float4*)g_na2)[ni];
    float4 o;
    o.x = q.x * nq.x + a.x * na.x * 0.5f;
    o.y = q.y * nq.y + a.y * na.y * 0.5f;
    o.z = q.z * nq.z + a.z * na.z * 0.5f;
    o.w = q.w * nq.w + a.w * na.w * 0.5f;
    ((float4*)fqo)[i4] = o;
}

// ---------------- conv1: bf16-split tensor implicit GEMM (proven) ----------------
__global__ void __launch_bounds__(256, 2) k_conv1(const float* __restrict__ f_q,
                                                  const float* __restrict__ f_s,
                                                  const float* __restrict__ b1) {
    __shared__ __align__(16) unsigned smW[2][2][16][36];  // [buf][hi/lo][k][oc72h]
    __shared__ __align__(16) unsigned smI[2][2][16][68];  // [buf][hi/lo][k][pix136h]
    int b = blockIdx.z, oc0 = blockIdx.y * 64, pix0 = blockIdx.x * 128;
    int tid = threadIdx.x, lane = tid & 31, wid = tid >> 5;
    int wm = (wid >> 2) * 32, wn = (wid & 3) * 32;
    int kr = tid >> 4, mc = (tid & 15) * 8;

    int kA = (lane & 7) + ((lane >> 4) << 3);
    int cA = ((lane >> 3) & 1) << 3;
    int kB = (lane & 7) + (((lane >> 3) & 1) << 3);
    int cB = (lane >> 4) << 3;
    unsigned baseW = (unsigned)__cvta_generic_to_shared(&smW[0][0][0][0]);
    unsigned baseI = (unsigned)__cvta_generic_to_shared(&smI[0][0][0][0]);
    unsigned offA = (unsigned)(kA * 144 + (cA + wm) * 2);
    unsigned offB = (unsigned)(kB * 272 + (cB + wn) * 2);

    const float* fqp = f_q + (size_t)b * CC * HW;
    const float* fsp = f_s + (size_t)b * CC * HW;

    int pp0 = pix0 + mc;
    int py = pp0 >> 5, px0v = pp0 & 31;
    int wtt = (tid & 127);
    int wrow = wtt >> 3, wcol8 = (wtt & 7) * 8;
    bool whalf = (tid < 128);

    float c[2][4][4];
#pragma unroll
    for (int f = 0; f < 2; f++)
#pragma unroll
        for (int g = 0; g < 4; g++) { c[f][g][0]=0.f; c[f][g][1]=0.f; c[f][g][2]=0.f; c[f][g][3]=0.f; }

    {
        uint4 wv;
        const __nv_bfloat16* wsrc = whalf ? g_wt1h : g_wt1l;
        wv = *(const uint4*)(wsrc + (size_t)(0 * 1024 + wrow) * 256 + oc0 + wcol8);
        float v[8];
        int ic = kr;
        const float* src = fqp + (size_t)ic * HW;
        int iy = py - 2;
        bool yok = ((unsigned)iy < 32u);
        const float* rowp = src + iy * 32;
#pragma unroll
        for (int j = 0; j < 8; j++) {
            int ix = px0v + j - 2;
            v[j] = (yok && ((unsigned)ix < 32u)) ? rowp[ix] : 0.f;
        }
        *(uint4*)&smW[0][whalf ? 0 : 1][wrow][wcol8 >> 1] = wv;
        unsigned h0,h1,l0,l1;
        unsigned* pIh = &smI[0][0][kr][mc >> 1];
        unsigned* pIl = &smI[0][1][kr][mc >> 1];
        float4 fa = make_float4(v[0], v[1], v[2], v[3]);
        float4 fb = make_float4(v[4], v[5], v[6], v[7]);
        cvt_hl(fa,h0,h1,l0,l1); pIh[0]=h0; pIh[1]=h1; pIl[0]=l0; pIl[1]=l1;
        cvt_hl(fb,h0,h1,l0,l1); pIh[2]=h0; pIh[3]=h1; pIl[2]=l0; pIl[3]=l1;
    }
    __syncthreads();

    int buf = 0;
    for (int kt = 0; kt < 576; kt++) {
        uint4 wv; float v[8];
        if (kt < 575) {
            int kn = kt + 1;
            int tap = kn >> 6, ict = kn & 63;
            int dy = 2 * (tap / 3) - 2, dx = 2 * (tap % 3) - 2;
            const __nv_bfloat16* wsrc = whalf ? g_wt1h : g_wt1l;
            wv = *(const uint4*)(wsrc + (size_t)(tap * 1024 + ict * 16 + wrow) * 256 + oc0 + wcol8);
            int ic = ict * 16 + kr;
            const float* src = (ic < 512 ? fqp + (size_t)ic * HW
                                         : fsp + (size_t)(ic - 512) * HW);
            int iy = py + dy;
            bool yok = ((unsigned)iy < 32u);
            const float* rowp = src + iy * 32;
#pragma unroll
            for (int j = 0; j < 8; j++) {
                int ix = px0v + j + dx;
                v[j] = (yok && ((unsigned)ix < 32u)) ? rowp[ix] : 0.f;
            }
        }
        unsigned bW = baseW + (unsigned)buf * 4608u;
        unsigned bI = baseI + (unsigned)buf * 8704u;
        unsigned a[8], al[8], bh[8], bl[8];
#pragma unroll
        for (int f = 0; f < 2; f++) ldsm4t(a  + 4 * f, bW + offA + f * 32);
#pragma unroll
        for (int f = 0; f < 2; f++) ldsm4t(al + 4 * f, bW + 2304u + offA + f * 32);
#pragma unroll
        for (int g2 = 0; g2 < 2; g2++) ldsm4t(bh + 4 * g2, bI + offB + g2 * 32);
#pragma unroll
        for (int g2 = 0; g2 < 2; g2++) ldsm4t(bl + 4 * g2, bI + 4352u + offB + g2 * 32);
#pragma unroll
        for (int f = 0; f < 2; f++)
#pragma unroll
            for (int g = 0; g < 4; g++) {
                mma_bf16(c[f][g], a  + 4 * f, bh + 2 * g);
                mma_bf16(c[f][g], a  + 4 * f, bl + 2 * g);
                mma_bf16(c[f][g], al + 4 * f, bh + 2 * g);
            }
        if (kt < 575) {
            int nb = buf ^ 1;
            *(uint4*)&smW[nb][whalf ? 0 : 1][wrow][wcol8 >> 1] = wv;
            unsigned h0,h1,l0,l1;
            unsigned* pIh = &smI[nb][0][kr][mc >> 1];
            unsigned* pIl = &smI[nb][1][kr][mc >> 1];
            float4 fa = make_float4(v[0], v[1], v[2], v[3]);
            float4 fb = make_float4(v[4], v[5], v[6], v[7]);
            cvt_hl(fa,h0,h1,l0,l1); pIh[0]=h0; pIh[1]=h1; pIl[0]=l0; pIl[1]=l1;
            cvt_hl(fb,h0,h1,l0,l1); pIh[2]=h0; pIh[3]=h1; pIl[2]=l0; pIl[3]=l1;
            __syncthreads();
            buf = nb;
        }
    }

    float* outp = g_c1 + (size_t)b * 262144;
#pragma unroll
    for (int f = 0; f < 2; f++) {
        int r0 = wm + f * 16 + (lane >> 2), r1 = r0 + 8;
        float bias0 = b1[oc0 + r0], bias1 = b1[oc0 + r1];
#pragma unroll
        for (int g = 0; g < 4; g++) {
            int cb = wn + g * 8 + (lane & 3) * 2;
            float2 o0 = make_float2(fmaxf(c[f][g][0] + bias0, 0.f),
                                    fmaxf(c[f][g][1] + bias0, 0.f));
            float2 o1 = make_float2(fmaxf(c[f][g][2] + bias1, 0.f),
                                    fmaxf(c[f][g][3] + bias1, 0.f));
            *(float2*)(outp + (size_t)(oc0 + r0) * HW + pix0 + cb) = o0;
            *(float2*)(outp + (size_t)(oc0 + r1) * HW + pix0 + cb) = o1;
        }
    }
}

// ---------------- conv2: bf16-split tensor implicit GEMM (conv1 template) ----------------
__global__ void __launch_bounds__(256, 2) k_conv2(const float* __restrict__ b2) {
    __shared__ __align__(16) unsigned smW[2][2][16][36];
    __shared__ __align__(16) unsigned smI[2][2][16][68];
    int b = blockIdx.z, oc0 = blockIdx.y * 64, pix0 = blockIdx.x * 128;
    int tid = threadIdx.x, lane = tid & 31, wid = tid >> 5;
    int wm = (wid >> 2) * 32, wn = (wid & 3) * 32;
    int kr = tid >> 4, mc = (tid & 15) * 8;

    int kA = (lane & 7) + ((lane >> 4) << 3);
    int cA = ((lane >> 3) & 1) << 3;
    int kB = (lane & 7) + (((lane >> 3) & 1) << 3);
    int cB = (lane >> 4) << 3;
    unsigned baseW = (unsigned)__cvta_generic_to_shared(&smW[0][0][0][0]);
    unsigned baseI = (unsigned)__cvta_generic_to_shared(&smI[0][0][0][0]);
    unsigned offA = (unsigned)(kA * 144 + (cA + wm) * 2);
    unsigned offB = (unsigned)(kB * 272 + (cB + wn) * 2);

    const float* c1p = g_c1 + (size_t)b * 262144;

    int offp[8];
#pragma unroll
    for (int j = 0; j < 8; j++) {
        int p = pix0 + mc + j; if (p > 899) p = 899;
        offp[j] = (p / 30) * 32 + (p % 30);
    }
    int wtt = (tid & 127);
    int wrow = wtt >> 3, wcol8 = (wtt & 7) * 8;
    bool whalf = (tid < 128);

    float c[2][4][4];
#pragma unroll
    for (int f = 0; f < 2; f++)
#pragma unroll
        for (int g = 0; g < 4; g++) { c[f][g][0]=0.f; c[f][g][1]=0.f; c[f][g][2]=0.f; c[f][g][3]=0.f; }

    {   // prologue kt=0: tap 0 (dy=0,dx=0), ict 0
        uint4 wv;
        const __nv_bfloat16* wsrc = whalf ? g_wt2h : g_wt2l;
        wv = *(const uint4*)(wsrc + (size_t)wrow * 256 + oc0 + wcol8);
        float v[8];
        const float* src = c1p + (size_t)kr * HW;
#pragma unroll
        for (int j = 0; j < 8; j++) v[j] = src[offp[j]];
        *(uint4*)&smW[0][whalf ? 0 : 1][wrow][wcol8 >> 1] = wv;
        unsigned h0,h1,l0,l1;
        unsigned* pIh = &smI[0][0][kr][mc >> 1];
        unsigned* pIl = &smI[0][1][kr][mc >> 1];
        float4 fa = make_float4(v[0], v[1], v[2], v[3]);
        float4 fb = make_float4(v[4], v[5], v[6], v[7]);
        cvt_hl(fa,h0,h1,l0,l1); pIh[0]=h0; pIh[1]=h1; pIl[0]=l0; pIl[1]=l1;
        cvt_hl(fb,h0,h1,l0,l1); pIh[2]=h0; pIh[3]=h1; pIl[2]=l0; pIl[3]=l1;
    }
    __syncthreads();

    int buf = 0;
    for (int kt = 0; kt < 144; kt++) {
        uint4 wv; float v[8];
        if (kt < 143) {
            int kn = kt + 1;
            int tap = kn >> 4, ict = kn & 15;
            int doff = (tap / 3) * 32 + (tap % 3);
            const __nv_bfloat16* wsrc = whalf ? g_wt2h : g_wt2l;
            wv = *(const uint4*)(wsrc + (size_t)(tap * 256 + ict * 16 + wrow) * 256 + oc0 + wcol8);
            const float* src = c1p + (size_t)(ict * 16 + kr) * HW;
#pragma unroll
            for (int j = 0; j < 8; j++) v[j] = src[offp[j] + doff];
        }
        unsigned bW = baseW + (unsigned)buf * 4608u;
        unsigned bI = baseI + (unsigned)buf * 8704u;
        unsigned a[8], al[8], bh[8], bl[8];
#pragma unroll
        for (int f = 0; f < 2; f++) ldsm4t(a  + 4 * f, bW + offA + f * 32);
#pragma unroll
        for (int f = 0; f < 2; f++) ldsm4t(al + 4 * f, bW + 2304u + offA + f * 32);
#pragma unroll
        for (int g2 = 0; g2 < 2; g2++) ldsm4t(bh + 4 * g2, bI + offB + g2 * 32);
#pragma unroll
        for (int g2 = 0; g2 < 2; g2++) ldsm4t(bl + 4 * g2, bI + 4352u + offB + g2 * 32);
#pragma unroll
        for (int f = 0; f < 2; f++)
#pragma unroll
            for (int g = 0; g < 4; g++) {
                mma_bf16(c[f][g], a  + 4 * f, bh + 2 * g);
                mma_bf16(c[f][g], a  + 4 * f, bl + 2 * g);
                mma_bf16(c[f][g], al + 4 * f, bh + 2 * g);
            }
        if (kt < 143) {
            int nb = buf ^ 1;
            *(uint4*)&smW[nb][whalf ? 0 : 1][wrow][wcol8 >> 1] = wv;
            unsigned h0,h1,l0,l1;
            unsigned* pIh = &smI[nb][0][kr][mc >> 1];
            unsigned* pIl = &smI[nb][1][kr][mc >> 1];
            float4 fa = make_float4(v[0], v[1], v[2], v[3]);
            float4 fb = make_float4(v[4], v[5], v[6], v[7]);
            cvt_hl(fa,h0,h1,l0,l1); pIh[0]=h0; pIh[1]=h1; pIl[0]=l0; pIl[1]=l1;
            cvt_hl(fb,h0,h1,l0,l1); pIh[2]=h0; pIh[3]=h1; pIl[2]=l0; pIl[3]=l1;
            __syncthreads();
            buf = nb;
        }
    }

    float* outp = g_c2 + (size_t)b * 230400;
#pragma unroll
    for (int f = 0; f < 2; f++) {
        int r0 = wm + f * 16 + (lane >> 2), r1 = r0 + 8;
        float bias0 = b2[oc0 + r0], bias1 = b2[oc0 + r1];
#pragma unroll
        for (int g = 0; g < 4; g++) {
            int cb = wn + g * 8 + (lane & 3) * 2;
            int p0 = pix0 + cb;                // even; p0<900 => p0+1<=899
            if (p0 < 900) {
                *(float2*)(outp + (size_t)(oc0 + r0) * 900 + p0) =
                    make_float2(c[f][g][0] + bias0, c[f][g][1] + bias0);
                *(float2*)(outp + (size_t)(oc0 + r1) * 900 + p0) =
                    make_float2(c[f][g][2] + bias1, c[f][g][3] + bias1);
            }
        }
    }
}

// ---------------- 3x3 stride-3 maxpool: 30x30 -> 10x10 ----------------
__global__ void k_pool() {
    int oc = blockIdx.x, b = blockIdx.y;
    int t = threadIdx.x;
    if (t >= 100) return;
    int y = t / 10, x = t % 10;
    const float* in = g_c2 + ((size_t)b * 256 + oc) * 900;
    float m = -3.4e38f;
#pragma unroll
    for (int dy = 0; dy < 3; dy++)
#pragma unroll
        for (int dx = 0; dx < 3; dx++)
            m = fmaxf(m, in[(3 * y + dy) * 30 + 3 * x + dx]);
    g_pool[((size_t)b * 256 + oc) * 100 + t] = m;
}

// ---------------- conv3 (3x3 VALID, 10x10 -> 8x8) + mean -> weight[b] ----------------
__global__ void k_conv3(const float* __restrict__ w3, const float* __restrict__ b3,
                        float* __restrict__ wout) {
    int b = blockIdx.x;
    int tid = threadIdx.x;
    int o = tid >> 2, part = tid & 3;
    int oy = o >> 3, ox = o & 7;
    float s = 0.f;
    for (int ic = part * 64; ic < part * 64 + 64; ic++) {
        const float* pp = g_pool + ((size_t)b * 256 + ic) * 100 + oy * 10 + ox;
        const float* wp = w3 + ic * 9;
#pragma unroll
        for (int ky = 0; ky < 3; ky++)
#pragma unroll
            for (int kx = 0; kx < 3; kx++)
                s = fmaf(pp[ky * 10 + kx], wp[ky * 3 + kx], s);
    }
    s += __shfl_down_sync(0xffffffffu, s, 1);
    s += __shfl_down_sync(0xffffffffu, s, 2);
    __shared__ float sh[64];
    if (part == 0) sh[o] = s;
    __syncthreads();
    if (tid < 32) {
        float v = sh[tid] + sh[tid + 32];
#pragma unroll
        for (int off = 16; off; off >>= 1) v += __shfl_xor_sync(0xffffffffu, v, off);
        if (tid == 0) wout[b] = v * (1.0f / 64.0f) + b3[0];
    }
}

// ---------------- launch ----------------
extern "C" void kernel_launch(void* const* d_in, const int* in_sizes, int n_in,
                              void* d_out, int out_size) {
    const float* fq_feats = (const float*)d_in[0];
    const float* fs_feats = (const float*)d_in[1];
    const float* f_q = (const float*)d_in[2];
    const float* f_s = (const float*)d_in[3];
    const float* w1 = (const float*)d_in[4];
    const float* b1 = (const float*)d_in[5];
    const float* w2 = (const float*)d_in[6];
    const float* b2 = (const float*)d_in[7];
    const float* w3 = (const float*)d_in[8];
    const float* b3 = (const float*)d_in[9];

    float* out     = (float*)d_out;
    float* fq_out  = out;                       // [4,512,32,32]
    float* att_out = out + 2097152;             // [4,512,32,32]
    float* w_out   = out + 4194304;             // [1,4]

    k_twt1<<<9216, 256>>>(w1);
    k_twt2<<<2304, 256>>>(w2);
    k_norms<<<dim3(4, 36, 2), 256>>>(fq_feats, fs_feats);
    k_corr<<<dim3(8, 8, 4), 256>>>(fq_feats, fs_feats);
    k_softmax<<<4096, 256>>>();
    k_att<<<dim3(8, 4, 4), 256>>>(f_s, att_out);
    k_norm2<<<dim3(4, 4, 2), 256>>>(f_q, att_out);
    k_fqout<<<2048, 256>>>(f_q, att_out, fq_out);
    k_conv1<<<dim3(8, 4, 4), 256>>>(f_q, f_s, b1);
    k_conv2<<<dim3(8, 4, 4), 256>>>(b2);
    k_pool<<<dim3(256, 4), 128>>>();
    k_conv3<<<4, 256>>>(w3, b3, w_out);
}

// round 9
// speedup vs baseline: 2.8184x; 1.1484x over previous
#include <cuda_runtime.h>
#include <cuda_bf16.h>

#define LL 9
#define BB 4
#define CC 512
#define HW 1024

// ---------------- scratch (device globals; no allocation) ----------------
__device__ __align__(16) float g_invq[LL*BB*HW];
__device__ __align__(16) float g_invs[LL*BB*HW];
__device__ __align__(16) float g_corr[(size_t)BB*HW*HW];   // 16 MB, reused as attn
__device__ __align__(16) float g_c1[BB*256*HW];            // conv1 out [b][256][32*32]
__device__ __align__(16) float g_c1pa[BB*256*HW];          // conv1 K-split partials
__device__ __align__(16) float g_c1pb[BB*256*HW];
__device__ __align__(16) float g_attpa[BB*CC*HW];          // att K-split partials
__device__ __align__(16) float g_attpb[BB*CC*HW];
__device__ __align__(16) float g_c2[BB*256*900];           // conv2 out [b][256][30*30]
__device__ __align__(16) float g_pool[BB*256*100];         // pooled [b][256][10*10]
__device__ __align__(16) __nv_bfloat16 g_wt1h[9*1024*256]; // w1 hi [tap][ic][oc]
__device__ __align__(16) __nv_bfloat16 g_wt1l[9*1024*256]; // w1 lo [tap][ic][oc]
__device__ __align__(16) __nv_bfloat16 g_wt2h[9*256*256];  // w2 hi [tap][ic][oc]
__device__ __align__(16) __nv_bfloat16 g_wt2l[9*256*256];  // w2 lo [tap][ic][oc]
__device__ __align__(16) float g_nq2[BB*HW];
__device__ __align__(16) float g_na2[BB*HW];

// ---------------- helpers ----------------
__device__ __forceinline__ void ldsm4t(unsigned* r, unsigned addr) {
    asm volatile("ldmatrix.sync.aligned.m8n8.x4.trans.shared.b16 {%0,%1,%2,%3}, [%4];\n"
        : "=r"(r[0]), "=r"(r[1]), "=r"(r[2]), "=r"(r[3]) : "r"(addr));
}
__device__ __forceinline__ void ldsm4(unsigned* r, unsigned addr) {
    asm volatile("ldmatrix.sync.aligned.m8n8.x4.shared.b16 {%0,%1,%2,%3}, [%4];\n"
        : "=r"(r[0]), "=r"(r[1]), "=r"(r[2]), "=r"(r[3]) : "r"(addr));
}
__device__ __forceinline__ void mma_bf16(float* c, const unsigned* a, const unsigned* b) {
    asm volatile(
        "mma.sync.aligned.m16n8k16.row.col.f32.bf16.bf16.f32 "
        "{%0,%1,%2,%3}, {%4,%5,%6,%7}, {%8,%9}, {%0,%1,%2,%3};\n"
        : "+f"(c[0]), "+f"(c[1]), "+f"(c[2]), "+f"(c[3])
        : "r"(a[0]), "r"(a[1]), "r"(a[2]), "r"(a[3]), "r"(b[0]), "r"(b[1]));
}
// split float4 -> hi bf16x2 pair + lo bf16x2 pair (packed as unsigned)
__device__ __forceinline__ void cvt_hl(float4 v, unsigned& h0, unsigned& h1,
                                       unsigned& l0, unsigned& l1) {
    __nv_bfloat162 H0 = __floats2bfloat162_rn(v.x, v.y);
    __nv_bfloat162 H1 = __floats2bfloat162_rn(v.z, v.w);
    __nv_bfloat162 L0 = __floats2bfloat162_rn(v.x - __bfloat162float(H0.x),
                                              v.y - __bfloat162float(H0.y));
    __nv_bfloat162 L1 = __floats2bfloat162_rn(v.z - __bfloat162float(H1.x),
                                              v.w - __bfloat162float(H1.y));
    h0 = *(unsigned*)&H0; h1 = *(unsigned*)&H1;
    l0 = *(unsigned*)&L0; l1 = *(unsigned*)&L1;
}

// ---------------- weight prep ----------------
__global__ void k_twt1(const float* __restrict__ w1) {
    int i = blockIdx.x * 256 + threadIdx.x;          // < 2359296
    float v = w1[i];
    int oc = i / 9216; int r = i % 9216; int ic = r / 9; int tap = r % 9;
    __nv_bfloat16 h = __float2bfloat16(v);
    __nv_bfloat16 lo = __float2bfloat16(v - __bfloat162float(h));
    int o = tap * 262144 + ic * 256 + oc;
    g_wt1h[o] = h; g_wt1l[o] = lo;
}
__global__ void k_twt2(const float* __restrict__ w2) {
    int i = blockIdx.x * 256 + threadIdx.x;          // < 589824
    float v = w2[i];
    int oc = i / 2304; int r = i % 2304; int ic = r / 9; int tap = r % 9;
    __nv_bfloat16 h = __float2bfloat16(v);
    __nv_bfloat16 lo = __float2bfloat16(v - __bfloat162float(h));
    int o = tap * 65536 + ic * 256 + oc;
    g_wt2h[o] = h; g_wt2l[o] = lo;
}

// ---------------- per-level per-pixel inverse channel norms ----------------
__global__ void k_norms(const float* __restrict__ fq, const float* __restrict__ fs) {
    int lb  = blockIdx.y;                             // 0..35 (l*B+b)
    int pix = blockIdx.x * 256 + threadIdx.x;         // 0..1023
    const float* src = (blockIdx.z == 0 ? fq : fs) + (size_t)lb * CC * HW + pix;
    float ss = 0.f;
#pragma unroll 8
    for (int c = 0; c < CC; c++) { float v = src[(size_t)c * HW]; ss = fmaf(v, v, ss); }
    float inv = 1.0f / fmaxf(sqrtf(ss), 1e-12f);
    (blockIdx.z == 0 ? g_invq : g_invs)[lb * HW + pix] = inv;
}

// ---------------- corr: bf16-split tensor-core (proven) ----------------
__global__ void __launch_bounds__(256, 2) k_corr(const float* __restrict__ fq,
                                                 const float* __restrict__ fs) {
    __shared__ __align__(16) unsigned smq[2][4][16][68];  // 68 u32 = 136 halves
    int b  = blockIdx.z;
    int m0 = blockIdx.y * 128, n0 = blockIdx.x * 128;
    int tid = threadIdx.x, lane = tid & 31, wid = tid >> 5;
    int wm = (wid >> 2) * 64, wn = (wid & 3) * 32;
    int kr = tid >> 4, mc = (tid & 15) * 8;           // loader: 16 k-rows x 8 floats

    int kA = (lane & 7) + ((lane >> 4) << 3);
    int cA = ((lane >> 3) & 1) << 3;
    int kB = (lane & 7) + (((lane >> 3) & 1) << 3);
    int cB = (lane >> 4) << 3;
    unsigned smbase = (unsigned)__cvta_generic_to_shared(&smq[0][0][0][0]);
    unsigned offA = (unsigned)(kA * 272 + (cA + wm) * 2);
    unsigned offB = (unsigned)(kB * 272 + (cB + wn) * 2);

    float* outp = g_corr + (size_t)b * HW * HW + (size_t)m0 * HW + n0;

    for (int l = 0; l < LL; l++) {
        const float* Ag = fq + (size_t)(l * BB + b) * CC * HW + m0;
        const float* Bg = fs + (size_t)(l * BB + b) * CC * HW + n0;

        float c[4][4][4];
#pragma unroll
        for (int f = 0; f < 4; f++)
#pragma unroll
            for (int g = 0; g < 4; g++) { c[f][g][0]=0.f; c[f][g][1]=0.f; c[f][g][2]=0.f; c[f][g][3]=0.f; }

        __syncthreads();                              // smem reuse across levels
        {   // prologue: k-tile 0 -> buf 0
            float4 a0g = *(const float4*)(Ag + (size_t)kr * HW + mc);
            float4 a1g = *(const float4*)(Ag + (size_t)kr * HW + mc + 4);
            float4 b0g = *(const float4*)(Bg + (size_t)kr * HW + mc);
            float4 b1g = *(const float4*)(Bg + (size_t)kr * HW + mc + 4);
            unsigned h0,h1,l0,l1;
            unsigned* pAh = &smq[0][0][kr][mc >> 1];
            unsigned* pAl = &smq[0][1][kr][mc >> 1];
            unsigned* pBh = &smq[0][2][kr][mc >> 1];
            unsigned* pBl = &smq[0][3][kr][mc >> 1];
            cvt_hl(a0g,h0,h1,l0,l1); pAh[0]=h0; pAh[1]=h1; pAl[0]=l0; pAl[1]=l1;
            cvt_hl(a1g,h0,h1,l0,l1); pAh[2]=h0; pAh[3]=h1; pAl[2]=l0; pAl[3]=l1;
            cvt_hl(b0g,h0,h1,l0,l1); pBh[0]=h0; pBh[1]=h1; pBl[0]=l0; pBl[1]=l1;
            cvt_hl(b1g,h0,h1,l0,l1); pBh[2]=h0; pBh[3]=h1; pBl[2]=l0; pBl[3]=l1;
        }
        __syncthreads();

        int buf = 0;
        for (int kt = 0; kt < 32; kt++) {
            float4 a0g, a1g, b0g, b1g;
            if (kt < 31) {
                int k0 = (kt + 1) * 16;
                a0g = *(const float4*)(Ag + (size_t)(k0 + kr) * HW + mc);
                a1g = *(const float4*)(Ag + (size_t)(k0 + kr) * HW + mc + 4);
                b0g = *(const float4*)(Bg + (size_t)(k0 + kr) * HW + mc);
                b1g = *(const float4*)(Bg + (size_t)(k0 + kr) * HW + mc + 4);
            }
            unsigned base = smbase + (unsigned)buf * 17408u;
            unsigned a[16], bh[8], bl[8];
#pragma unroll
            for (int f = 0; f < 4; f++) ldsm4t(a + 4 * f, base + offA + f * 32);
#pragma unroll
            for (int g2 = 0; g2 < 2; g2++) ldsm4t(bh + 4 * g2, base + 2u * 4352u + offB + g2 * 32);
#pragma unroll
            for (int g2 = 0; g2 < 2; g2++) ldsm4t(bl + 4 * g2, base + 3u * 4352u + offB + g2 * 32);
#pragma unroll
            for (int f = 0; f < 4; f++)
#pragma unroll
                for (int g = 0; g < 4; g++) {
                    mma_bf16(c[f][g], a + 4 * f, bh + 2 * g);
                    mma_bf16(c[f][g], a + 4 * f, bl + 2 * g);
                }
#pragma unroll
            for (int f = 0; f < 4; f++) ldsm4t(a + 4 * f, base + 4352u + offA + f * 32);
#pragma unroll
            for (int f = 0; f < 4; f++)
#pragma unroll
                for (int g = 0; g < 4; g++)
                    mma_bf16(c[f][g], a + 4 * f, bh + 2 * g);

            if (kt < 31) {
                int nb = buf ^ 1;
                unsigned h0,h1,l0,l1;
                unsigned* pAh = &smq[nb][0][kr][mc >> 1];
                unsigned* pAl = &smq[nb][1][kr][mc >> 1];
                unsigned* pBh = &smq[nb][2][kr][mc >> 1];
                unsigned* pBl = &smq[nb][3][kr][mc >> 1];
                cvt_hl(a0g,h0,h1,l0,l1); pAh[0]=h0; pAh[1]=h1; pAl[0]=l0; pAl[1]=l1;
                cvt_hl(a1g,h0,h1,l0,l1); pAh[2]=h0; pAh[3]=h1; pAl[2]=l0; pAl[3]=l1;
                cvt_hl(b0g,h0,h1,l0,l1); pBh[0]=h0; pBh[1]=h1; pBl[0]=l0; pBl[1]=l1;
                cvt_hl(b1g,h0,h1,l0,l1); pBh[2]=h0; pBh[3]=h1; pBl[2]=l0; pBl[3]=l1;
                __syncthreads();
                buf = nb;
            }
        }

        const float* iq = g_invq + (l * BB + b) * HW + m0;
        const float* is = g_invs + (l * BB + b) * HW + n0;
#pragma unroll
        for (int f = 0; f < 4; f++) {
            int r0 = wm + f * 16 + (lane >> 2), r1 = r0 + 8;
            float q0 = iq[r0], q1 = iq[r1];
#pragma unroll
            for (int g = 0; g < 4; g++) {
                int cb = wn + g * 8 + (lane & 3) * 2;
                float s0 = is[cb], s1 = is[cb + 1];
                float v00 = fmaxf(c[f][g][0] * q0 * s0, 0.f);
                float v01 = fmaxf(c[f][g][1] * q0 * s1, 0.f);
                float v10 = fmaxf(c[f][g][2] * q1 * s0, 0.f);
                float v11 = fmaxf(c[f][g][3] * q1 * s1, 0.f);
                float2* p0 = (float2*)(outp + (size_t)r0 * HW + cb);
                float2* p1 = (float2*)(outp + (size_t)r1 * HW + cb);
                if (l == 0) {
                    *p0 = make_float2(v00, v01);
                    *p1 = make_float2(v10, v11);
                } else {
                    float2 o0 = *p0, o1 = *p1;
                    o0.x += v00; o0.y += v01; o1.x += v10; o1.y += v11;
                    *p0 = o0; *p1 = o1;
                }
            }
        }
    }
}

// ---------------- row softmax (scale = TEMP/L folds the mean) ----------------
__global__ void k_softmax() {
    float* r = g_corr + (size_t)blockIdx.x * HW;      // blockIdx.x = b*1024 + q
    int tid = threadIdx.x, wid = tid >> 5, lane = tid & 31;
    const float sc = 20.0f / 9.0f;
    float4 v = ((const float4*)r)[tid];
    v.x *= sc; v.y *= sc; v.z *= sc; v.w *= sc;
    float mx = fmaxf(fmaxf(v.x, v.y), fmaxf(v.z, v.w));
#pragma unroll
    for (int o = 16; o; o >>= 1) mx = fmaxf(mx, __shfl_xor_sync(0xffffffffu, mx, o));
    __shared__ float sh[8];
    if (lane == 0) sh[wid] = mx;
    __syncthreads();
    float m = sh[0];
#pragma unroll
    for (int k = 1; k < 8; k++) m = fmaxf(m, sh[k]);
    v.x = __expf(v.x - m); v.y = __expf(v.y - m);
    v.z = __expf(v.z - m); v.w = __expf(v.w - m);
    float s = v.x + v.y + v.z + v.w;
#pragma unroll
    for (int o = 16; o; o >>= 1) s += __shfl_xor_sync(0xffffffffu, s, o);
    __syncthreads();
    if (lane == 0) sh[wid] = s;
    __syncthreads();
    float tot = 0.f;
#pragma unroll
    for (int k = 0; k < 8; k++) tot += sh[k];
    float inv = 1.0f / tot;
    v.x *= inv; v.y *= inv; v.z *= inv; v.w *= inv;
    ((float4*)r)[tid] = v;
}

// ---------------- k_att: bf16-split MMA, K-split by 2 (half = z&1) ----------------
__global__ void __launch_bounds__(256, 2) k_att(const float* __restrict__ fs_in) {
    __shared__ __align__(16) uint4 smA[2][2][2][128];   // [buf][hl][kb][row]
    __shared__ __align__(16) uint4 smB[2][2][2][128];
    int b = blockIdx.z >> 1, half = blockIdx.z & 1;
    int m0 = blockIdx.y * 128, n0 = blockIdx.x * 128;
    int tid = threadIdx.x, lane = tid & 31, wid = tid >> 5;
    int wm = (wid >> 2) * 64, wn = (wid & 3) * 32;
    int lrow = tid >> 1, lkb = tid & 1;

    const float* Ag = fs_in + (size_t)b * CC * HW + (size_t)m0 * HW + half * 512;
    const float* Bg = g_corr + (size_t)b * HW * HW + (size_t)n0 * HW + half * 512;

    int rsel = ((lane >> 3) & 1) * 8 + (lane & 7);
    int kbsel = lane >> 4;
    unsigned baseA = (unsigned)__cvta_generic_to_shared(&smA[0][0][0][0]);
    unsigned baseB = (unsigned)__cvta_generic_to_shared(&smB[0][0][0][0]);
    unsigned offA = (unsigned)(kbsel * 2048 + (wm + rsel) * 16);     // + f*256
    unsigned offB = (unsigned)(kbsel * 2048 + (wn + rsel) * 16);     // + gg*256

    float c[4][4][4];
#pragma unroll
    for (int f = 0; f < 4; f++)
#pragma unroll
        for (int g = 0; g < 4; g++) { c[f][g][0]=0.f; c[f][g][1]=0.f; c[f][g][2]=0.f; c[f][g][3]=0.f; }

    {   // prologue: k-tile 0
        float4 a0g = *(const float4*)(Ag + (size_t)lrow * HW + lkb * 8);
        float4 a1g = *(const float4*)(Ag + (size_t)lrow * HW + lkb * 8 + 4);
        float4 b0g = *(const float4*)(Bg + (size_t)lrow * HW + lkb * 8);
        float4 b1g = *(const float4*)(Bg + (size_t)lrow * HW + lkb * 8 + 4);
        unsigned h0,h1,l0,l1,h2,h3,l2,l3;
        cvt_hl(a0g,h0,h1,l0,l1); cvt_hl(a1g,h2,h3,l2,l3);
        smA[0][0][lkb][lrow] = make_uint4(h0,h1,h2,h3);
        smA[0][1][lkb][lrow] = make_uint4(l0,l1,l2,l3);
        cvt_hl(b0g,h0,h1,l0,l1); cvt_hl(b1g,h2,h3,l2,l3);
        smB[0][0][lkb][lrow] = make_uint4(h0,h1,h2,h3);
        smB[0][1][lkb][lrow] = make_uint4(l0,l1,l2,l3);
    }
    __syncthreads();

    int buf = 0;
    for (int kt = 0; kt < 32; kt++) {
        float4 a0g, a1g, b0g, b1g;
        if (kt < 31) {
            int k0 = (kt + 1) * 16 + lkb * 8;
            a0g = *(const float4*)(Ag + (size_t)lrow * HW + k0);
            a1g = *(const float4*)(Ag + (size_t)lrow * HW + k0 + 4);
            b0g = *(const float4*)(Bg + (size_t)lrow * HW + k0);
            b1g = *(const float4*)(Bg + (size_t)lrow * HW + k0 + 4);
        }
        unsigned bA = baseA + (unsigned)buf * 8192u;
        unsigned bB = baseB + (unsigned)buf * 8192u;
        unsigned a[16], bh[8], bl[8], t[4];
#pragma unroll
        for (int f = 0; f < 4; f++) ldsm4(a + 4 * f, bA + offA + f * 256);
#pragma unroll
        for (int gg = 0; gg < 2; gg++) {
            ldsm4(t, bB + offB + gg * 256);
            bh[gg*4+0]=t[0]; bh[gg*4+1]=t[2]; bh[gg*4+2]=t[1]; bh[gg*4+3]=t[3];
        }
#pragma unroll
        for (int gg = 0; gg < 2; gg++) {
            ldsm4(t, bB + 4096u + offB + gg * 256);
            bl[gg*4+0]=t[0]; bl[gg*4+1]=t[2]; bl[gg*4+2]=t[1]; bl[gg*4+3]=t[3];
        }
#pragma unroll
        for (int f = 0; f < 4; f++)
#pragma unroll
            for (int g = 0; g < 4; g++) {
                mma_bf16(c[f][g], a + 4 * f, bh + 2 * g);
                mma_bf16(c[f][g], a + 4 * f, bl + 2 * g);
            }
#pragma unroll
        for (int f = 0; f < 4; f++) ldsm4(a + 4 * f, bA + 4096u + offA + f * 256);
#pragma unroll
        for (int f = 0; f < 4; f++)
#pragma unroll
            for (int g = 0; g < 4; g++)
                mma_bf16(c[f][g], a + 4 * f, bh + 2 * g);

        if (kt < 31) {
            int nb = buf ^ 1;
            unsigned h0,h1,l0,l1,h2,h3,l2,l3;
            cvt_hl(a0g,h0,h1,l0,l1); cvt_hl(a1g,h2,h3,l2,l3);
            smA[nb][0][lkb][lrow] = make_uint4(h0,h1,h2,h3);
            smA[nb][1][lkb][lrow] = make_uint4(l0,l1,l2,l3);
            cvt_hl(b0g,h0,h1,l0,l1); cvt_hl(b1g,h2,h3,l2,l3);
            smB[nb][0][lkb][lrow] = make_uint4(h0,h1,h2,h3);
            smB[nb][1][lkb][lrow] = make_uint4(l0,l1,l2,l3);
            __syncthreads();
            buf = nb;
        }
    }

    float* outp = (half ? g_attpb : g_attpa) + (size_t)b * CC * HW + (size_t)m0 * HW + n0;
#pragma unroll
    for (int f = 0; f < 4; f++) {
        int r0 = wm + f * 16 + (lane >> 2), r1 = r0 + 8;
#pragma unroll
        for (int g = 0; g < 4; g++) {
            int cb = wn + g * 8 + (lane & 3) * 2;
            *(float2*)(outp + (size_t)r0 * HW + cb) = make_float2(c[f][g][0], c[f][g][1]);
            *(float2*)(outp + (size_t)r1 * HW + cb) = make_float2(c[f][g][2], c[f][g][3]);
        }
    }
}

// att_out = pa + pb
__global__ void k_attcomb(float* __restrict__ attout) {
    int i4 = blockIdx.x * 256 + threadIdx.x;          // < 524288
    float4 a = ((const float4*)g_attpa)[i4];
    float4 bb = ((const float4*)g_attpb)[i4];
    ((float4*)attout)[i4] = make_float4(a.x + bb.x, a.y + bb.y, a.z + bb.z, a.w + bb.w);
}

// ---------------- inverse channel norms of f_q and att_fq ----------------
__global__ void k_norm2(const float* __restrict__ f_q, const float* __restrict__ att) {
    int b   = blockIdx.y;
    int pix = blockIdx.x * 256 + threadIdx.x;
    const float* src = (blockIdx.z == 0 ? f_q : att) + (size_t)b * CC * HW + pix;
    float ss = 0.f;
#pragma unroll 8
    for (int c = 0; c < CC; c++) { float v = src[(size_t)c * HW]; ss = fmaf(v, v, ss); }
    float inv = 1.0f / fmaxf(sqrtf(ss), 1e-12f);
    (blockIdx.z == 0 ? g_nq2 : g_na2)[b * HW + pix] = inv;
}

// ---------------- fq = l2n(f_q) + 0.5*l2n(att_fq) ----------------
__global__ void k_fqout(const float* __restrict__ f_q, const float* __restrict__ att,
                        float* __restrict__ fqo) {
    int i4 = blockIdx.x * 256 + threadIdx.x;          // < 524288
    int base = i4 * 4;
    int b = base >> 19;
    int pix = base & 1023;
    float4 q = ((const float4*)f_q)[i4];
    float4 a = ((const float4*)att)[i4];
    int ni = (b * HW + pix) >> 2;
    float4 nq = ((const float4*)g_nq2)[ni];
    float4 na = ((const float4*)g_na2)[ni];
    float4 o;
    o.x = q.x * nq.x + a.x * na.x * 0.5f;
    o.y = q.y * nq.y + a.y * na.y * 0.5f;
    o.z = q.z * nq.z + a.z * na.z * 0.5f;
    o.w = q.w * nq.w + a.w * na.w * 0.5f;
    ((float4*)fqo)[i4] = o;
}

// ---------------- conv1: bf16-split tensor implicit GEMM, K-split by 2 ----------------
__global__ void __launch_bounds__(256, 2) k_conv1(const float* __restrict__ f_q,
                                                  const float* __restrict__ f_s) {
    __shared__ __align__(16) unsigned smW[2][2][16][36];  // [buf][hi/lo][k][oc72h]
    __shared__ __align__(16) unsigned smI[2][2][16][68];  // [buf][hi/lo][k][pix136h]
    int b = blockIdx.z >> 1, half = blockIdx.z & 1;
    int oc0 = blockIdx.y * 64, pix0 = blockIdx.x * 128;
    int tid = threadIdx.x, lane = tid & 31, wid = tid >> 5;
    int wm = (wid >> 2) * 32, wn = (wid & 3) * 32;
    int kr = tid >> 4, mc = (tid & 15) * 8;

    int kA = (lane & 7) + ((lane >> 4) << 3);
    int cA = ((lane >> 3) & 1) << 3;
    int kB = (lane & 7) + (((lane >> 3) & 1) << 3);
    int cB = (lane >> 4) << 3;
    unsigned baseW = (unsigned)__cvta_generic_to_shared(&smW[0][0][0][0]);
    unsigned baseI = (unsigned)__cvta_generic_to_shared(&smI[0][0][0][0]);
    unsigned offA = (unsigned)(kA * 144 + (cA + wm) * 2);
    unsigned offB = (unsigned)(kB * 272 + (cB + wn) * 2);

    const float* fqp = f_q + (size_t)b * CC * HW;
    const float* fsp = f_s + (size_t)b * CC * HW;

    int pp0 = pix0 + mc;
    int py = pp0 >> 5, px0v = pp0 & 31;
    int wtt = (tid & 127);
    int wrow = wtt >> 3, wcol8 = (wtt & 7) * 8;
    bool whalf = (tid < 128);
    int kbase = half * 288;                           // global k-tile base

    float c[2][4][4];
#pragma unroll
    for (int f = 0; f < 2; f++)
#pragma unroll
        for (int g = 0; g < 4; g++) { c[f][g][0]=0.f; c[f][g][1]=0.f; c[f][g][2]=0.f; c[f][g][3]=0.f; }

    {   // prologue: global k-tile kbase
        int tap = kbase >> 6, ict = kbase & 63;
        int dy = 2 * (tap / 3) - 2, dx = 2 * (tap % 3) - 2;
        uint4 wv;
        const __nv_bfloat16* wsrc = whalf ? g_wt1h : g_wt1l;
        wv = *(const uint4*)(wsrc + (size_t)(tap * 1024 + ict * 16 + wrow) * 256 + oc0 + wcol8);
        float v[8];
        int ic = ict * 16 + kr;
        const float* src = (ic < 512 ? fqp + (size_t)ic * HW
                                     : fsp + (size_t)(ic - 512) * HW);
        int iy = py + dy;
        bool yok = ((unsigned)iy < 32u);
        const float* rowp = src + iy * 32;
#pragma unroll
        for (int j = 0; j < 8; j++) {
            int ix = px0v + j + dx;
            v[j] = (yok && ((unsigned)ix < 32u)) ? rowp[ix] : 0.f;
        }
        *(uint4*)&smW[0][whalf ? 0 : 1][wrow][wcol8 >> 1] = wv;
        unsigned h0,h1,l0,l1;
        unsigned* pIh = &smI[0][0][kr][mc >> 1];
        unsigned* pIl = &smI[0][1][kr][mc >> 1];
        float4 fa = make_float4(v[0], v[1], v[2], v[3]);
        float4 fb = make_float4(v[4], v[5], v[6], v[7]);
        cvt_hl(fa,h0,h1,l0,l1); pIh[0]=h0; pIh[1]=h1; pIl[0]=l0; pIl[1]=l1;
        cvt_hl(fb,h0,h1,l0,l1); pIh[2]=h0; pIh[3]=h1; pIl[2]=l0; pIl[3]=l1;
    }
    __syncthreads();

    int buf = 0;
    for (int kt = 0; kt < 288; kt++) {
        uint4 wv; float v[8];
        if (kt < 287) {
            int kn = kbase + kt + 1;
            int tap = kn >> 6, ict = kn & 63;
            int dy = 2 * (tap / 3) - 2, dx = 2 * (tap % 3) - 2;
            const __nv_bfloat16* wsrc = whalf ? g_wt1h : g_wt1l;
            wv = *(const uint4*)(wsrc + (size_t)(tap * 1024 + ict * 16 + wrow) * 256 + oc0 + wcol8);
            int ic = ict * 16 + kr;
            const float* src = (ic < 512 ? fqp + (size_t)ic * HW
                                         : fsp + (size_t)(ic - 512) * HW);
            int iy = py + dy;
            bool yok = ((unsigned)iy < 32u);
            const float* rowp = src + iy * 32;
#pragma unroll
            for (int j = 0; j < 8; j++) {
                int ix = px0v + j + dx;
                v[j] = (yok && ((unsigned)ix < 32u)) ? rowp[ix] : 0.f;
            }
        }
        unsigned bW = baseW + (unsigned)buf * 4608u;
        unsigned bI = baseI + (unsigned)buf * 8704u;
        unsigned a[8], al[8], bh[8], bl[8];
#pragma unroll
        for (int f = 0; f < 2; f++) ldsm4t(a  + 4 * f, bW + offA + f * 32);
#pragma unroll
        for (int f = 0; f < 2; f++) ldsm4t(al + 4 * f, bW + 2304u + offA + f * 32);
#pragma unroll
        for (int g2 = 0; g2 < 2; g2++) ldsm4t(bh + 4 * g2, bI + offB + g2 * 32);
#pragma unroll
        for (int g2 = 0; g2 < 2; g2++) ldsm4t(bl + 4 * g2, bI + 4352u + offB + g2 * 32);
#pragma unroll
        for (int f = 0; f < 2; f++)
#pragma unroll
            for (int g = 0; g < 4; g++) {
                mma_bf16(c[f][g], a  + 4 * f, bh + 2 * g);
                mma_bf16(c[f][g], a  + 4 * f, bl + 2 * g);
                mma_bf16(c[f][g], al + 4 * f, bh + 2 * g);
            }
        if (kt < 287) {
            int nb = buf ^ 1;
            *(uint4*)&smW[nb][whalf ? 0 : 1][wrow][wcol8 >> 1] = wv;
            unsigned h0,h1,l0,l1;
            unsigned* pIh = &smI[nb][0][kr][mc >> 1];
            unsigned* pIl = &smI[nb][1][kr][mc >> 1];
            float4 fa = make_float4(v[0], v[1], v[2], v[3]);
            float4 fb = make_float4(v[4], v[5], v[6], v[7]);
            cvt_hl(fa,h0,h1,l0,l1); pIh[0]=h0; pIh[1]=h1; pIl[0]=l0; pIl[1]=l1;
            cvt_hl(fb,h0,h1,l0,l1); pIh[2]=h0; pIh[3]=h1; pIl[2]=l0; pIl[3]=l1;
            __syncthreads();
            buf = nb;
        }
    }

    float* outp = (half ? g_c1pb : g_c1pa) + (size_t)b * 262144;
#pragma unroll
    for (int f = 0; f < 2; f++) {
        int r0 = wm + f * 16 + (lane >> 2), r1 = r0 + 8;
#pragma unroll
        for (int g = 0; g < 4; g++) {
            int cb = wn + g * 8 + (lane & 3) * 2;
            *(float2*)(outp + (size_t)(oc0 + r0) * HW + pix0 + cb) =
                make_float2(c[f][g][0], c[f][g][1]);
            *(float2*)(outp + (size_t)(oc0 + r1) * HW + pix0 + cb) =
                make_float2(c[f][g][2], c[f][g][3]);
        }
    }
}

// c1 = relu(pa + pb + bias)
__global__ void k_c1comb(const float* __restrict__ b1) {
    int i4 = blockIdx.x * 256 + threadIdx.x;          // < 262144
    float4 a = ((const float4*)g_c1pa)[i4];
    float4 bb = ((const float4*)g_c1pb)[i4];
    int oc = (i4 & 65535) >> 8;                       // per-b block: 65536 f4, 256 f4 per oc
    float bias = b1[oc];
    float4 o;
    o.x = fmaxf(a.x + bb.x + bias, 0.f);
    o.y = fmaxf(a.y + bb.y + bias, 0.f);
    o.z = fmaxf(a.z + bb.z + bias, 0.f);
    o.w = fmaxf(a.w + bb.w + bias, 0.f);
    ((float4*)g_c1)[i4] = o;
}

// ---------------- conv2: bf16-split tensor implicit GEMM (conv1 template) ----------------
__global__ void __launch_bounds__(256, 2) k_conv2(const float* __restrict__ b2) {
    __shared__ __align__(16) unsigned smW[2][2][16][36];
    __shared__ __align__(16) unsigned smI[2][2][16][68];
    int b = blockIdx.z, oc0 = blockIdx.y * 64, pix0 = blockIdx.x * 128;
    int tid = threadIdx.x, lane = tid & 31, wid = tid >> 5;
    int wm = (wid >> 2) * 32, wn = (wid & 3) * 32;
    int kr = tid >> 4, mc = (tid & 15) * 8;

    int kA = (lane & 7) + ((lane >> 4) << 3);
    int cA = ((lane >> 3) & 1) << 3;
    int kB = (lane & 7) + (((lane >> 3) & 1) << 3);
    int cB = (lane >> 4) << 3;
    unsigned baseW = (unsigned)__cvta_generic_to_shared(&smW[0][0][0][0]);
    unsigned baseI = (unsigned)__cvta_generic_to_shared(&smI[0][0][0][0]);
    unsigned offA = (unsigned)(kA * 144 + (cA + wm) * 2);
    unsigned offB = (unsigned)(kB * 272 + (cB + wn) * 2);

    const float* c1p = g_c1 + (size_t)b * 262144;

    int offp[8];
#pragma unroll
    for (int j = 0; j < 8; j++) {
        int p = pix0 + mc + j; if (p > 899) p = 899;
        offp[j] = (p / 30) * 32 + (p % 30);
    }
    int wtt = (tid & 127);
    int wrow = wtt >> 3, wcol8 = (wtt & 7) * 8;
    bool whalf = (tid < 128);

    float c[2][4][4];
#pragma unroll
    for (int f = 0; f < 2; f++)
#pragma unroll
        for (int g = 0; g < 4; g++) { c[f][g][0]=0.f; c[f][g][1]=0.f; c[f][g][2]=0.f; c[f][g][3]=0.f; }

    {   // prologue kt=0: tap 0 (dy=0,dx=0), ict 0
        uint4 wv;
        const __nv_bfloat16* wsrc = whalf ? g_wt2h : g_wt2l;
        wv = *(const uint4*)(wsrc + (size_t)wrow * 256 + oc0 + wcol8);
        float v[8];
        const float* src = c1p + (size_t)kr * HW;
#pragma unroll
        for (int j = 0; j < 8; j++) v[j] = src[offp[j]];
        *(uint4*)&smW[0][whalf ? 0 : 1][wrow][wcol8 >> 1] = wv;
        unsigned h0,h1,l0,l1;
        unsigned* pIh = &smI[0][0][kr][mc >> 1];
        unsigned* pIl = &smI[0][1][kr][mc >> 1];
        float4 fa = make_float4(v[0], v[1], v[2], v[3]);
        float4 fb = make_float4(v[4], v[5], v[6], v[7]);
        cvt_hl(fa,h0,h1,l0,l1); pIh[0]=h0; pIh[1]=h1; pIl[0]=l0; pIl[1]=l1;
        cvt_hl(fb,h0,h1,l0,l1); pIh[2]=h0; pIh[3]=h1; pIl[2]=l0; pIl[3]=l1;
    }
    __syncthreads();

    int buf = 0;
    for (int kt = 0; kt < 144; kt++) {
        uint4 wv; float v[8];
        if (kt < 143) {
            int kn = kt + 1;
            int tap = kn >> 4, ict = kn & 15;
            int doff = (tap / 3) * 32 + (tap % 3);
            const __nv_bfloat16* wsrc = whalf ? g_wt2h : g_wt2l;
            wv = *(const uint4*)(wsrc + (size_t)(tap * 256 + ict * 16 + wrow) * 256 + oc0 + wcol8);
            const float* src = c1p + (size_t)(ict * 16 + kr) * HW;
#pragma unroll
            for (int j = 0; j < 8; j++) v[j] = src[offp[j] + doff];
        }
        unsigned bW = baseW + (unsigned)buf * 4608u;
        unsigned bI = baseI + (unsigned)buf * 8704u;
        unsigned a[8], al[8], bh[8], bl[8];
#pragma unroll
        for (int f = 0; f < 2; f++) ldsm4t(a  + 4 * f, bW + offA + f * 32);
#pragma unroll
        for (int f = 0; f < 2; f++) ldsm4t(al + 4 * f, bW + 2304u + offA + f * 32);
#pragma unroll
        for (int g2 = 0; g2 < 2; g2++) ldsm4t(bh + 4 * g2, bI + offB + g2 * 32);
#pragma unroll
        for (int g2 = 0; g2 < 2; g2++) ldsm4t(bl + 4 * g2, bI + 4352u + offB + g2 * 32);
#pragma unroll
        for (int f = 0; f < 2; f++)
#pragma unroll
            for (int g = 0; g < 4; g++) {
                mma_bf16(c[f][g], a  + 4 * f, bh + 2 * g);
                mma_bf16(c[f][g], a  + 4 * f, bl + 2 * g);
                mma_bf16(c[f][g], al + 4 * f, bh + 2 * g);
            }
        if (kt < 143) {
            int nb = buf ^ 1;
            *(uint4*)&smW[nb][whalf ? 0 : 1][wrow][wcol8 >> 1] = wv;
            unsigned h0,h1,l0,l1;
            unsigned* pIh = &smI[nb][0][kr][mc >> 1];
            unsigned* pIl = &smI[nb][1][kr][mc >> 1];
            float4 fa = make_float4(v[0], v[1], v[2], v[3]);
            float4 fb = make_float4(v[4], v[5], v[6], v[7]);
            cvt_hl(fa,h0,h1,l0,l1); pIh[0]=h0; pIh[1]=h1; pIl[0]=l0; pIl[1]=l1;
            cvt_hl(fb,h0,h1,l0,l1); pIh[2]=h0; pIh[3]=h1; pIl[2]=l0; pIl[3]=l1;
            __syncthreads();
            buf = nb;
        }
    }

    float* outp = g_c2 + (size_t)b * 230400;
#pragma unroll
    for (int f = 0; f < 2; f++) {
        int r0 = wm + f * 16 + (lane >> 2), r1 = r0 + 8;
        float bias0 = b2[oc0 + r0], bias1 = b2[oc0 + r1];
#pragma unroll
        for (int g = 0; g < 4; g++) {
            int cb = wn + g * 8 + (lane & 3) * 2;
            int p0 = pix0 + cb;                // even; p0<900 => p0+1<=899
            if (p0 < 900) {
                *(float2*)(outp + (size_t)(oc0 + r0) * 900 + p0) =
                    make_float2(c[f][g][0] + bias0, c[f][g][1] + bias0);
                *(float2*)(outp + (size_t)(oc0 + r1) * 900 + p0) =
                    make_float2(c[f][g][2] + bias1, c[f][g][3] + bias1);
            }
        }
    }
}

// ---------------- 3x3 stride-3 maxpool: 30x30 -> 10x10 ----------------
__global__ void k_pool() {
    int oc = blockIdx.x, b = blockIdx.y;
    int t = threadIdx.x;
    if (t >= 100) return;
    int y = t / 10, x = t % 10;
    const float* in = g_c2 + ((size_t)b * 256 + oc) * 900;
    float m = -3.4e38f;
#pragma unroll
    for (int dy = 0; dy < 3; dy++)
#pragma unroll
        for (int dx = 0; dx < 3; dx++)
            m = fmaxf(m, in[(3 * y + dy) * 30 + 3 * x + dx]);
    g_pool[((size_t)b * 256 + oc) * 100 + t] = m;
}

// ---------------- conv3 (3x3 VALID, 10x10 -> 8x8) + mean -> weight[b] ----------------
__global__ void k_conv3(const float* __restrict__ w3, const float* __restrict__ b3,
                        float* __restrict__ wout) {
    int b = blockIdx.x;
    int tid = threadIdx.x;
    int o = tid >> 2, part = tid & 3;
    int oy = o >> 3, ox = o & 7;
    float s = 0.f;
    for (int ic = part * 64; ic < part * 64 + 64; ic++) {
        const float* pp = g_pool + ((size_t)b * 256 + ic) * 100 + oy * 10 + ox;
        const float* wp = w3 + ic * 9;
#pragma unroll
        for (int ky = 0; ky < 3; ky++)
#pragma unroll
            for (int kx = 0; kx < 3; kx++)
                s = fmaf(pp[ky * 10 + kx], wp[ky * 3 + kx], s);
    }
    s += __shfl_down_sync(0xffffffffu, s, 1);
    s += __shfl_down_sync(0xffffffffu, s, 2);
    __shared__ float sh[64];
    if (part == 0) sh[o] = s;
    __syncthreads();
    if (tid < 32) {
        float v = sh[tid] + sh[tid + 32];
#pragma unroll
        for (int off = 16; off; off >>= 1) v += __shfl_xor_sync(0xffffffffu, v, off);
        if (tid == 0) wout[b] = v * (1.0f / 64.0f) + b3[0];
    }
}

// ---------------- launch ----------------
extern "C" void kernel_launch(void* const* d_in, const int* in_sizes, int n_in,
                              void* d_out, int out_size) {
    const float* fq_feats = (const float*)d_in[0];
    const float* fs_feats = (const float*)d_in[1];
    const float* f_q = (const float*)d_in[2];
    const float* f_s = (const float*)d_in[3];
    const float* w1 = (const float*)d_in[4];
    const float* b1 = (const float*)d_in[5];
    const float* w2 = (const float*)d_in[6];
    const float* b2 = (const float*)d_in[7];
    const float* w3 = (const float*)d_in[8];
    const float* b3 = (const float*)d_in[9];

    float* out     = (float*)d_out;
    float* fq_out  = out;                       // [4,512,32,32]
    float* att_out = out + 2097152;             // [4,512,32,32]
    float* w_out   = out + 4194304;             // [1,4]

    k_twt1<<<9216, 256>>>(w1);
    k_twt2<<<2304, 256>>>(w2);
    k_norms<<<dim3(4, 36, 2), 256>>>(fq_feats, fs_feats);
    k_corr<<<dim3(8, 8, 4), 256>>>(fq_feats, fs_feats);
    k_softmax<<<4096, 256>>>();
    k_att<<<dim3(8, 4, 8), 256>>>(f_s);
    k_attcomb<<<2048, 256>>>(att_out);
    k_norm2<<<dim3(4, 4, 2), 256>>>(f_q, att_out);
    k_fqout<<<2048, 256>>>(f_q, att_out, fq_out);
    k_conv1<<<dim3(8, 4, 8), 256>>>(f_q, f_s);
    k_c1comb<<<1024, 256>>>(b1);
    k_conv2<<<dim3(8, 4, 4), 256>>>(b2);
    k_pool<<<dim3(256, 4), 128>>>();
    k_conv3<<<4, 256>>>(w3, b3, w_out);
}